// round 9
// baseline (speedup 1.0000x reference)
#include <cuda_runtime.h>
#include <cuda_fp16.h>
#include <cstdint>
#include <cstddef>

// Problem constants
#define Bsz 8
#define Hn  16
#define Nn  4096
#define DHn 64
#define Kn  128
#define Dn  1024
#define HD  (Dn / 2)     // u32 (fp16-pair) row stride

// Device scratch (no allocs allowed)
__device__ uint32_t g_kph[Bsz * Kn * HD];          // projected K hi limb (fp16 pairs)
__device__ uint32_t g_kpl[Bsz * Kn * HD];          // projected K lo limb
__device__ uint32_t g_vph[Bsz * Kn * HD];          // projected V hi limb
__device__ uint32_t g_vpl[Bsz * Kn * HD];          // projected V lo limb
__device__ uint32_t g_PTh[2 * Kn * (Nn / 2)];      // P^T hi f16 pairs [w][k][n/2]
__device__ uint32_t g_PTl[2 * Kn * (Nn / 2)];      // P^T lo f16 pairs

typedef unsigned long long u64;

// ---------------------------------------------------------------------------
// helpers (fp16 limbs)
// ---------------------------------------------------------------------------
__device__ __forceinline__ uint32_t cvt2h(float hi_elem, float lo_elem) {
    uint32_t r;
    asm("cvt.rn.f16x2.f32 %0, %1, %2;" : "=r"(r) : "f"(hi_elem), "f"(lo_elem));
    return r;
}
__device__ __forceinline__ float f16lo(uint32_t p) {
    return __half2float(__ushort_as_half((unsigned short)(p & 0xffffu)));
}
__device__ __forceinline__ float f16hi(uint32_t p) {
    return __half2float(__ushort_as_half((unsigned short)(p >> 16)));
}

#define SWZ128(x) ((x) ^ (((x) >> 3) & 0x70))
#define SWZ256(x) ((x) ^ (((x) >> 4) & 0x70))

#define LDSM4(r, a) \
    asm volatile("ldmatrix.sync.aligned.m8n8.x4.shared.b16 {%0,%1,%2,%3}, [%4];" \
        : "=r"((r)[0]), "=r"((r)[1]), "=r"((r)[2]), "=r"((r)[3]) : "r"(a))
#define LDSM4T(r, a) \
    asm volatile("ldmatrix.sync.aligned.m8n8.x4.trans.shared.b16 {%0,%1,%2,%3}, [%4];" \
        : "=r"((r)[0]), "=r"((r)[1]), "=r"((r)[2]), "=r"((r)[3]) : "r"(a))
#define MMA_F16(c, a, b0v, b1v) \
    asm volatile("mma.sync.aligned.m16n8k16.row.col.f32.f16.f16.f32 " \
        "{%0,%1,%2,%3}, {%4,%5,%6,%7}, {%8,%9}, {%0,%1,%2,%3};" \
        : "+f"((c)[0]), "+f"((c)[1]), "+f"((c)[2]), "+f"((c)[3]) \
        : "r"((a)[0]), "r"((a)[1]), "r"((a)[2]), "r"((a)[3]), "r"(b0v), "r"(b1v))

__device__ __forceinline__ uint32_t smem_u32(const void* p) {
    uint32_t a;
    asm("{ .reg .u64 t; cvta.to.shared.u64 t, %1; cvt.u32.u64 %0, t; }" : "=r"(a) : "l"(p));
    return a;
}

// split a float4 (optionally scaled) into hi/lo f16x2 pairs
__device__ __forceinline__ void split4h(float4 v, float s, uint2& h, uint2& l) {
    v.x *= s; v.y *= s; v.z *= s; v.w *= s;
    uint32_t h01 = cvt2h(v.y, v.x);
    uint32_t h23 = cvt2h(v.w, v.z);
    float h0 = f16lo(h01), h1 = f16hi(h01);
    float h2 = f16lo(h23), h3 = f16hi(h23);
    uint32_t l01 = cvt2h(v.y - h1, v.x - h0);
    uint32_t l23 = cvt2h(v.w - h3, v.z - h2);
    h = make_uint2(h01, h23);
    l = make_uint2(l01, l23);
}

// ============================================================================
// Kernel 0: transpose P [4096 n][128 k] -> split-f16 PT [w][128 k][4096 n]
// ============================================================================
__global__ void __launch_bounds__(256) ptrans_kernel(
    const float* __restrict__ pk, const float* __restrict__ pv)
{
    __shared__ float sT[128][33];
    const int t  = threadIdx.x;
    const int n0 = blockIdx.x * 32;
    const int w  = blockIdx.y;
    const float* __restrict__ P = w ? pv : pk;

    #pragma unroll
    for (int i = 0; i < 16; i++) {
        int idx = t + 256 * i;
        int r = idx >> 7, c = idx & 127;
        sT[c][r] = P[(size_t)(n0 + r) * Kn + c];
    }
    __syncthreads();

    uint32_t* __restrict__ oh = g_PTh + (size_t)w * Kn * (Nn / 2);
    uint32_t* __restrict__ ol = g_PTl + (size_t)w * Kn * (Nn / 2);
    #pragma unroll
    for (int i = 0; i < 8; i++) {
        int idx = t + 256 * i;
        int k = idx >> 4, pr = idx & 15;
        float x0 = sT[k][2 * pr], x1 = sT[k][2 * pr + 1];
        uint32_t h = cvt2h(x1, x0);
        float h0 = f16lo(h), h1 = f16hi(h);
        uint32_t l = cvt2h(x1 - h1, x0 - h0);
        size_t o = (size_t)k * (Nn / 2) + (n0 >> 1) + pr;
        oh[o] = h;
        ol[o] = l;
    }
}

// ============================================================================
// Kernel 1: mma.sync f16-split projection (3-pass); epilogue emits fp16 limbs
// ============================================================================
#define PJ_AHI 0
#define PJ_ALO 16384
#define PJ_BHI 32768
#define PJ_BLO 49152
#define PJ_STAGE 65536
#define PJ_SMEM (2 * PJ_STAGE)

__global__ void __launch_bounds__(512, 1) proj_mma_kernel(
    const float* __restrict__ keys, const float* __restrict__ values)
{
    const int dt = blockIdx.x;
    const int b  = blockIdx.y;
    const int w  = blockIdx.z;

    const float* __restrict__ X = (w ? values : keys) + (size_t)b * Nn * Dn + dt * 128;
    const uint32_t* __restrict__ PTh = g_PTh + (size_t)w * Kn * (Nn / 2);
    const uint32_t* __restrict__ PTl = g_PTl + (size_t)w * Kn * (Nn / 2);
    uint32_t* __restrict__ Gh = (w ? g_vph : g_kph) + (size_t)b * Kn * HD + dt * 64;
    uint32_t* __restrict__ Gl = (w ? g_vpl : g_kpl) + (size_t)b * Kn * HD + dt * 64;

    extern __shared__ __align__(1024) unsigned char dsm[];
    const uint32_t sbase = smem_u32(dsm);

    const int tid  = threadIdx.x;
    const int wid  = tid >> 5, lane = tid & 31;
    const int warp_m = (wid >> 2) * 32;
    const int warp_d = (wid & 3) * 32;

    float acc[2][4][4];
    #pragma unroll
    for (int i = 0; i < 2; i++)
        #pragma unroll
        for (int j = 0; j < 4; j++)
            #pragma unroll
            for (int q = 0; q < 4; q++) acc[i][j][q] = 0.0f;

    uint4  pA[4];
    float4 pB[4];

    #pragma unroll
    for (int u = 0; u < 2; u++) {
        int idx = tid + 512 * u;
        int row = idx >> 3, c8 = idx & 7;
        size_t o = (size_t)row * (Nn / 2) + c8 * 4;
        pA[u]     = *(const uint4*)&PTh[o];
        pA[2 + u] = *(const uint4*)&PTl[o];
    }
    #pragma unroll
    for (int u = 0; u < 4; u++) {
        int idx = tid + 512 * u;
        int row = idx >> 5, c4 = idx & 31;
        pB[u] = *(const float4*)&X[(size_t)row * Dn + c4 * 4];
    }

    for (int c = 0; c < 64; ++c) {
        unsigned char* st = dsm + (c & 1) * PJ_STAGE;

        #pragma unroll
        for (int u = 0; u < 2; u++) {
            int idx = tid + 512 * u;
            int row = idx >> 3, c8 = idx & 7;
            uint32_t off = SWZ128((uint32_t)(row * 128 + c8 * 16));
            *(uint4*)(st + PJ_AHI + off) = pA[u];
            *(uint4*)(st + PJ_ALO + off) = pA[2 + u];
        }
        #pragma unroll
        for (int u = 0; u < 4; u++) {
            int idx = tid + 512 * u;
            int row = idx >> 5, c4 = idx & 31;
            uint2 hh, ll;
            split4h(pB[u], 1.0f, hh, ll);
            uint32_t off = SWZ256((uint32_t)(row * 256 + c4 * 8));
            *(uint2*)(st + PJ_BHI + off) = hh;
            *(uint2*)(st + PJ_BLO + off) = ll;
        }
        __syncthreads();

        if (c < 63) {
            int nb = (c + 1) * 64;
            #pragma unroll
            for (int u = 0; u < 2; u++) {
                int idx = tid + 512 * u;
                int row = idx >> 3, c8 = idx & 7;
                size_t o = (size_t)row * (Nn / 2) + (nb >> 1) + c8 * 4;
                pA[u]     = *(const uint4*)&PTh[o];
                pA[2 + u] = *(const uint4*)&PTl[o];
            }
            #pragma unroll
            for (int u = 0; u < 4; u++) {
                int idx = tid + 512 * u;
                int row = idx >> 5, c4 = idx & 31;
                pB[u] = *(const float4*)&X[(size_t)(nb + row) * Dn + c4 * 4];
            }
        }

        const uint32_t sA = sbase + (c & 1) * PJ_STAGE;
        const uint32_t sB = sA + PJ_BHI;
        #pragma unroll
        for (int ks = 0; ks < 4; ks++) {
            uint32_t ah[2][4], al[2][4];
            #pragma unroll
            for (int mi = 0; mi < 2; mi++) {
                uint32_t off = SWZ128((uint32_t)((warp_m + mi * 16 + (lane & 15)) * 128
                                                 + ks * 32 + (lane >> 4) * 16));
                LDSM4(ah[mi], sA + PJ_AHI + off);
                LDSM4(al[mi], sA + PJ_ALO + off);
            }
            #pragma unroll
            for (int g2 = 0; g2 < 2; g2++) {
                uint32_t offb = SWZ256((uint32_t)((ks * 16 + (lane & 15)) * 256
                                                  + warp_d * 2 + g2 * 32 + (lane >> 4) * 16));
                uint32_t bh[4], bl[4];
                LDSM4T(bh, sB + offb);
                LDSM4T(bl, sB + (PJ_BLO - PJ_BHI) + offb);
                #pragma unroll
                for (int mi = 0; mi < 2; mi++) {
                    #pragma unroll
                    for (int jj = 0; jj < 2; jj++) {
                        float* cc = acc[mi][g2 * 2 + jj];
                        MMA_F16(cc, ah[mi], bh[jj * 2], bh[jj * 2 + 1]);
                        MMA_F16(cc, ah[mi], bl[jj * 2], bl[jj * 2 + 1]);
                        MMA_F16(cc, al[mi], bh[jj * 2], bh[jj * 2 + 1]);
                    }
                }
            }
        }
        __syncthreads();
    }

    // ---- epilogue: split accumulators to fp16 limbs, store pairs ----
    #pragma unroll
    for (int mi = 0; mi < 2; mi++) {
        #pragma unroll
        for (int j = 0; j < 4; j++) {
            int row = warp_m + mi * 16 + (lane >> 2);
            int cp  = (warp_d + j * 8) / 2 + (lane & 3);   // u32 pair column
            float a0 = acc[mi][j][0], a1 = acc[mi][j][1];
            float a2 = acc[mi][j][2], a3 = acc[mi][j][3];
            uint32_t h0 = cvt2h(a1, a0);
            uint32_t l0 = cvt2h(a1 - f16hi(h0), a0 - f16lo(h0));
            uint32_t h1 = cvt2h(a3, a2);
            uint32_t l1 = cvt2h(a3 - f16hi(h1), a2 - f16lo(h1));
            Gh[(size_t)row * HD + cp]       = h0;
            Gl[(size_t)row * HD + cp]       = l0;
            Gh[(size_t)(row + 8) * HD + cp] = h1;
            Gl[(size_t)(row + 8) * HD + cp] = l1;
        }
    }
}

// ============================================================================
// Kernel 2: tensor-core attention; 2 tiles (256 rows) per CTA.
//   K/V limbs copied directly from gmem (pre-split by proj) — no ALU.
//   Per tile: Q fill+split -> GEMM1 (3-pass) -> softmax (P single fp16)
//             -> GEMM2 (2-pass) -> store.   P reuses the dead Q region.
// ============================================================================
#define AT_QHI  0
#define AT_QLO  16384
#define AT_PHI  0
#define AT_KHI  32768
#define AT_KLO  49152
#define AT_VHI  65536
#define AT_VLO  81920
#define AT_SMAX 98304
#define AT_SSUM 99328
#define AT_SMEM 100352

__global__ void __launch_bounds__(256, 2) attn_mma_kernel(
    const float* __restrict__ qg, float* __restrict__ outg)
{
    const int nt2 = blockIdx.x;    // 0..15 : 256-row group
    const int h   = blockIdx.y;
    const int b   = blockIdx.z;

    extern __shared__ __align__(1024) unsigned char smb[];
    const uint32_t sbase = smem_u32(smb);
    float* smax = (float*)(smb + AT_SMAX);
    float* ssum = (float*)(smb + AT_SSUM);

    const int tid  = threadIdx.x;
    const int wid  = tid >> 5, lane = tid & 31;
    const int g    = lane >> 2, tk = lane & 3;
    const int wm   = (wid >> 1) * 32;
    const int kh   = wid & 1;

    // ---- K/V limb fill (once per CTA; direct 16B copies) ----
    {
        const size_t kvb = (size_t)b * Kn * HD + h * 32;
        #pragma unroll
        for (int t = 0; t < 4; t++) {
            int idx = tid + 256 * t;
            int row = idx >> 3, u4 = idx & 7;
            size_t o = kvb + (size_t)row * HD + u4 * 4;
            uint32_t off = SWZ128((uint32_t)(row * 128 + u4 * 16));
            *(uint4*)(smb + AT_KHI + off) = *(const uint4*)&g_kph[o];
            *(uint4*)(smb + AT_KLO + off) = *(const uint4*)&g_kpl[o];
            *(uint4*)(smb + AT_VHI + off) = *(const uint4*)&g_vph[o];
            *(uint4*)(smb + AT_VLO + off) = *(const uint4*)&g_vpl[o];
        }
    }

    for (int tile = 0; tile < 2; tile++) {
        const size_t rowbase = (size_t)b * Nn + (size_t)nt2 * 256 + tile * 128;

        // ---- Q fill + split ----
        {
            const size_t qbase = rowbase * Dn + h * 64;
            #pragma unroll
            for (int t = 0; t < 8; t++) {
                int idx = tid + 256 * t;
                int row = idx >> 4, c4 = idx & 15;
                size_t go = (size_t)row * Dn + c4 * 4;
                uint32_t off = SWZ128((uint32_t)(row * 128 + c4 * 8));
                uint2 hh, ll;
                split4h(*(const float4*)&qg[qbase + go], 0.125f, hh, ll);
                *(uint2*)(smb + AT_QHI + off) = hh;
                *(uint2*)(smb + AT_QLO + off) = ll;
            }
        }
        __syncthreads();

        // ---- GEMM1: dots[128n x 128k]; warp tile 32n x 64k; 3-pass ----
        float acc[2][8][4];
        #pragma unroll
        for (int i = 0; i < 2; i++)
            #pragma unroll
            for (int j = 0; j < 8; j++)
                #pragma unroll
                for (int q = 0; q < 4; q++) acc[i][j][q] = 0.0f;

        {
            const int wk = kh * 64;
            #pragma unroll
            for (int ks = 0; ks < 4; ks++) {
                uint32_t ah[2][4], al[2][4];
                #pragma unroll
                for (int mi = 0; mi < 2; mi++) {
                    uint32_t off = SWZ128((uint32_t)((wm + mi * 16 + (lane & 15)) * 128
                                                     + ks * 32 + (lane >> 4) * 16));
                    LDSM4(ah[mi], sbase + AT_QHI + off);
                    LDSM4(al[mi], sbase + AT_QLO + off);
                }
                #pragma unroll
                for (int jj = 0; jj < 4; jj++) {
                    uint32_t offb = SWZ128((uint32_t)((wk + jj * 16 + (lane & 15)) * 128
                                                      + ks * 32 + (lane >> 4) * 16));
                    uint32_t bh[4], bl[4];
                    LDSM4(bh, sbase + AT_KHI + offb);
                    LDSM4(bl, sbase + AT_KLO + offb);
                    // non-trans B pairing: tile(2jj)=(r0,r2), tile(2jj+1)=(r1,r3)
                    #pragma unroll
                    for (int mi = 0; mi < 2; mi++) {
                        float* c0 = acc[mi][jj * 2];
                        MMA_F16(c0, ah[mi], bh[0], bh[2]);
                        MMA_F16(c0, ah[mi], bl[0], bl[2]);
                        MMA_F16(c0, al[mi], bh[0], bh[2]);
                        float* c1v = acc[mi][jj * 2 + 1];
                        MMA_F16(c1v, ah[mi], bh[1], bh[3]);
                        MMA_F16(c1v, ah[mi], bl[1], bl[3]);
                        MMA_F16(c1v, al[mi], bh[1], bh[3]);
                    }
                }
            }
        }

        // ---- softmax part 1: row max ----
        #pragma unroll
        for (int mi = 0; mi < 2; mi++) {
            #pragma unroll
            for (int h2 = 0; h2 < 2; h2++) {
                float m = acc[mi][0][h2 * 2];
                #pragma unroll
                for (int j = 0; j < 8; j++)
                    m = fmaxf(m, fmaxf(acc[mi][j][h2 * 2], acc[mi][j][h2 * 2 + 1]));
                m = fmaxf(m, __shfl_xor_sync(0xffffffffu, m, 1));
                m = fmaxf(m, __shfl_xor_sync(0xffffffffu, m, 2));
                if (tk == 0) smax[(wm + mi * 16 + g + h2 * 8) * 2 + kh] = m;
            }
        }
        __syncthreads();

        // ---- softmax part 2: exp, write SINGLE fp16 P (into dead Q region);
        //      accumulate rowsum from the ROUNDED P ----
        #pragma unroll
        for (int mi = 0; mi < 2; mi++) {
            #pragma unroll
            for (int h2 = 0; h2 < 2; h2++) {
                int row = wm + mi * 16 + g + h2 * 8;
                float M = fmaxf(smax[row * 2], smax[row * 2 + 1]);
                float s = 0.0f;
                #pragma unroll
                for (int j = 0; j < 8; j++) {
                    float x0 = __expf(acc[mi][j][h2 * 2]     - M);
                    float x1 = __expf(acc[mi][j][h2 * 2 + 1] - M);
                    uint32_t ph = cvt2h(x1, x0);
                    s += f16lo(ph) + f16hi(ph);
                    uint32_t off = SWZ256((uint32_t)(row * 256 + kh * 128 + j * 16 + tk * 4));
                    *(uint32_t*)(smb + AT_PHI + off) = ph;
                }
                s += __shfl_xor_sync(0xffffffffu, s, 1);
                s += __shfl_xor_sync(0xffffffffu, s, 2);
                if (tk == 0) ssum[row * 2 + kh] = s;
            }
        }
        __syncthreads();

        // ---- GEMM2: out = P . VV; 2-pass (P single, V 2-limb) ----
        float o[2][4][4];
        #pragma unroll
        for (int i = 0; i < 2; i++)
            #pragma unroll
            for (int j = 0; j < 4; j++)
                #pragma unroll
                for (int q = 0; q < 4; q++) o[i][j][q] = 0.0f;

        {
            const int wdh = kh * 32;
            #pragma unroll
            for (int ks = 0; ks < 8; ks++) {
                uint32_t ah[2][4];
                #pragma unroll
                for (int mi = 0; mi < 2; mi++) {
                    uint32_t off = SWZ256((uint32_t)((wm + mi * 16 + (lane & 15)) * 256
                                                     + ks * 32 + (lane >> 4) * 16));
                    LDSM4(ah[mi], sbase + AT_PHI + off);
                }
                #pragma unroll
                for (int g2 = 0; g2 < 2; g2++) {
                    uint32_t offb = SWZ128((uint32_t)((ks * 16 + (lane & 15)) * 128
                                                      + wdh * 2 + g2 * 32 + (lane >> 4) * 16));
                    uint32_t bh[4], bl[4];
                    LDSM4T(bh, sbase + AT_VHI + offb);
                    LDSM4T(bl, sbase + AT_VLO + offb);
                    // trans B pairing: tile(g2*2)=(r0,r1), tile(g2*2+1)=(r2,r3)
                    #pragma unroll
                    for (int mi = 0; mi < 2; mi++) {
                        #pragma unroll
                        for (int jj = 0; jj < 2; jj++) {
                            float* cc = o[mi][g2 * 2 + jj];
                            MMA_F16(cc, ah[mi], bh[jj * 2], bh[jj * 2 + 1]);
                            MMA_F16(cc, ah[mi], bl[jj * 2], bl[jj * 2 + 1]);
                        }
                    }
                }
            }
        }

        // ---- epilogue: normalize by 1/rowsum, store ----
        {
            const int wdh = kh * 32;
            const size_t obase = rowbase * Dn + h * 64;
            #pragma unroll
            for (int mi = 0; mi < 2; mi++) {
                int r0 = wm + mi * 16 + g;
                int r1 = r0 + 8;
                float ri0 = 1.0f / (ssum[r0 * 2] + ssum[r0 * 2 + 1]);
                float ri1 = 1.0f / (ssum[r1 * 2] + ssum[r1 * 2 + 1]);
                #pragma unroll
                for (int j = 0; j < 4; j++) {
                    int col = wdh + j * 8 + tk * 2;
                    *(float2*)&outg[obase + (size_t)r0 * Dn + col] =
                        make_float2(o[mi][j][0] * ri0, o[mi][j][1] * ri0);
                    *(float2*)&outg[obase + (size_t)r1 * Dn + col] =
                        make_float2(o[mi][j][2] * ri1, o[mi][j][3] * ri1);
                }
            }
        }
        __syncthreads();   // protect P/Q region before next tile's Q fill
    }
}

// ============================================================================
// Launch
// ============================================================================
extern "C" void kernel_launch(void* const* d_in, const int* in_sizes, int n_in,
                              void* d_out, int out_size)
{
    const float* q      = (const float*)d_in[0];
    const float* keys   = (const float*)d_in[1];
    const float* values = (const float*)d_in[2];
    const float* pk     = (const float*)d_in[3];
    const float* pv     = (const float*)d_in[4];
    float* out = (float*)d_out;

    cudaFuncSetAttribute(proj_mma_kernel,
                         cudaFuncAttributeMaxDynamicSharedMemorySize, PJ_SMEM);
    cudaFuncSetAttribute(attn_mma_kernel,
                         cudaFuncAttributeMaxDynamicSharedMemorySize, AT_SMEM);

    ptrans_kernel<<<dim3(Nn / 32, 2), 256>>>(pk, pv);
    proj_mma_kernel<<<dim3(8, Bsz, 2), 512, PJ_SMEM>>>(keys, values);
    attn_mma_kernel<<<dim3(16, Hn, Bsz), 256, AT_SMEM>>>(q, out);
}

// round 10
// speedup vs baseline: 1.0137x; 1.0137x over previous
#include <cuda_runtime.h>
#include <cuda_fp16.h>
#include <cstdint>
#include <cstddef>

// Problem constants
#define Bsz 8
#define Hn  16
#define Nn  4096
#define DHn 64
#define Kn  128
#define Dn  1024
#define HD  (Dn / 2)     // u32 (fp16-pair) row stride

// Device scratch (no allocs allowed)
__device__ uint32_t g_kph[Bsz * Kn * HD];          // projected K hi limb (fp16 pairs)
__device__ uint32_t g_kpl[Bsz * Kn * HD];          // projected K lo limb
__device__ uint32_t g_vph[Bsz * Kn * HD];          // projected V hi limb
__device__ uint32_t g_vpl[Bsz * Kn * HD];          // projected V lo limb
__device__ uint32_t g_PTh[2 * Kn * (Nn / 2)];      // P^T hi f16 pairs [w][k][n/2]
__device__ uint32_t g_PTl[2 * Kn * (Nn / 2)];      // P^T lo f16 pairs

typedef unsigned long long u64;

// ---------------------------------------------------------------------------
// helpers (fp16 limbs)
// ---------------------------------------------------------------------------
__device__ __forceinline__ uint32_t cvt2h(float hi_elem, float lo_elem) {
    uint32_t r;
    asm("cvt.rn.f16x2.f32 %0, %1, %2;" : "=r"(r) : "f"(hi_elem), "f"(lo_elem));
    return r;
}
__device__ __forceinline__ float f16lo(uint32_t p) {
    return __half2float(__ushort_as_half((unsigned short)(p & 0xffffu)));
}
__device__ __forceinline__ float f16hi(uint32_t p) {
    return __half2float(__ushort_as_half((unsigned short)(p >> 16)));
}

#define SWZ128(x) ((x) ^ (((x) >> 3) & 0x70))
#define SWZ256(x) ((x) ^ (((x) >> 4) & 0x70))

#define LDSM4(r, a) \
    asm volatile("ldmatrix.sync.aligned.m8n8.x4.shared.b16 {%0,%1,%2,%3}, [%4];" \
        : "=r"((r)[0]), "=r"((r)[1]), "=r"((r)[2]), "=r"((r)[3]) : "r"(a))
#define LDSM4T(r, a) \
    asm volatile("ldmatrix.sync.aligned.m8n8.x4.trans.shared.b16 {%0,%1,%2,%3}, [%4];" \
        : "=r"((r)[0]), "=r"((r)[1]), "=r"((r)[2]), "=r"((r)[3]) : "r"(a))
#define MMA_F16(c, a, b0v, b1v) \
    asm volatile("mma.sync.aligned.m16n8k16.row.col.f32.f16.f16.f32 " \
        "{%0,%1,%2,%3}, {%4,%5,%6,%7}, {%8,%9}, {%0,%1,%2,%3};" \
        : "+f"((c)[0]), "+f"((c)[1]), "+f"((c)[2]), "+f"((c)[3]) \
        : "r"((a)[0]), "r"((a)[1]), "r"((a)[2]), "r"((a)[3]), "r"(b0v), "r"(b1v))

__device__ __forceinline__ uint32_t smem_u32(const void* p) {
    uint32_t a;
    asm("{ .reg .u64 t; cvta.to.shared.u64 t, %1; cvt.u32.u64 %0, t; }" : "=r"(a) : "l"(p));
    return a;
}

// split a float4 (optionally scaled) into hi/lo f16x2 pairs
__device__ __forceinline__ void split4h(float4 v, float s, uint2& h, uint2& l) {
    v.x *= s; v.y *= s; v.z *= s; v.w *= s;
    uint32_t h01 = cvt2h(v.y, v.x);
    uint32_t h23 = cvt2h(v.w, v.z);
    float h0 = f16lo(h01), h1 = f16hi(h01);
    float h2 = f16lo(h23), h3 = f16hi(h23);
    uint32_t l01 = cvt2h(v.y - h1, v.x - h0);
    uint32_t l23 = cvt2h(v.w - h3, v.z - h2);
    h = make_uint2(h01, h23);
    l = make_uint2(l01, l23);
}

// ============================================================================
// Kernel 0: transpose P [4096 n][128 k] -> split-f16 PT [w][128 k][4096 n]
// ============================================================================
__global__ void __launch_bounds__(256) ptrans_kernel(
    const float* __restrict__ pk, const float* __restrict__ pv)
{
    __shared__ float sT[128][33];
    const int t  = threadIdx.x;
    const int n0 = blockIdx.x * 32;
    const int w  = blockIdx.y;
    const float* __restrict__ P = w ? pv : pk;

    #pragma unroll
    for (int i = 0; i < 16; i++) {
        int idx = t + 256 * i;
        int r = idx >> 7, c = idx & 127;
        sT[c][r] = P[(size_t)(n0 + r) * Kn + c];
    }
    __syncthreads();

    uint32_t* __restrict__ oh = g_PTh + (size_t)w * Kn * (Nn / 2);
    uint32_t* __restrict__ ol = g_PTl + (size_t)w * Kn * (Nn / 2);
    #pragma unroll
    for (int i = 0; i < 8; i++) {
        int idx = t + 256 * i;
        int k = idx >> 4, pr = idx & 15;
        float x0 = sT[k][2 * pr], x1 = sT[k][2 * pr + 1];
        uint32_t h = cvt2h(x1, x0);
        float h0 = f16lo(h), h1 = f16hi(h);
        uint32_t l = cvt2h(x1 - h1, x0 - h0);
        size_t o = (size_t)k * (Nn / 2) + (n0 >> 1) + pr;
        oh[o] = h;
        ol[o] = l;
    }
}

// ============================================================================
// Kernel 1: mma.sync f16-split projection (3-pass); epilogue emits fp16 limbs
// ============================================================================
#define PJ_AHI 0
#define PJ_ALO 16384
#define PJ_BHI 32768
#define PJ_BLO 49152
#define PJ_STAGE 65536
#define PJ_SMEM (2 * PJ_STAGE)

__global__ void __launch_bounds__(512, 1) proj_mma_kernel(
    const float* __restrict__ keys, const float* __restrict__ values)
{
    const int dt = blockIdx.x;
    const int b  = blockIdx.y;
    const int w  = blockIdx.z;

    const float* __restrict__ X = (w ? values : keys) + (size_t)b * Nn * Dn + dt * 128;
    const uint32_t* __restrict__ PTh = g_PTh + (size_t)w * Kn * (Nn / 2);
    const uint32_t* __restrict__ PTl = g_PTl + (size_t)w * Kn * (Nn / 2);
    uint32_t* __restrict__ Gh = (w ? g_vph : g_kph) + (size_t)b * Kn * HD + dt * 64;
    uint32_t* __restrict__ Gl = (w ? g_vpl : g_kpl) + (size_t)b * Kn * HD + dt * 64;

    extern __shared__ __align__(1024) unsigned char dsm[];
    const uint32_t sbase = smem_u32(dsm);

    const int tid  = threadIdx.x;
    const int wid  = tid >> 5, lane = tid & 31;
    const int warp_m = (wid >> 2) * 32;
    const int warp_d = (wid & 3) * 32;

    float acc[2][4][4];
    #pragma unroll
    for (int i = 0; i < 2; i++)
        #pragma unroll
        for (int j = 0; j < 4; j++)
            #pragma unroll
            for (int q = 0; q < 4; q++) acc[i][j][q] = 0.0f;

    uint4  pA[4];
    float4 pB[4];

    #pragma unroll
    for (int u = 0; u < 2; u++) {
        int idx = tid + 512 * u;
        int row = idx >> 3, c8 = idx & 7;
        size_t o = (size_t)row * (Nn / 2) + c8 * 4;
        pA[u]     = *(const uint4*)&PTh[o];
        pA[2 + u] = *(const uint4*)&PTl[o];
    }
    #pragma unroll
    for (int u = 0; u < 4; u++) {
        int idx = tid + 512 * u;
        int row = idx >> 5, c4 = idx & 31;
        pB[u] = *(const float4*)&X[(size_t)row * Dn + c4 * 4];
    }

    for (int c = 0; c < 64; ++c) {
        unsigned char* st = dsm + (c & 1) * PJ_STAGE;

        #pragma unroll
        for (int u = 0; u < 2; u++) {
            int idx = tid + 512 * u;
            int row = idx >> 3, c8 = idx & 7;
            uint32_t off = SWZ128((uint32_t)(row * 128 + c8 * 16));
            *(uint4*)(st + PJ_AHI + off) = pA[u];
            *(uint4*)(st + PJ_ALO + off) = pA[2 + u];
        }
        #pragma unroll
        for (int u = 0; u < 4; u++) {
            int idx = tid + 512 * u;
            int row = idx >> 5, c4 = idx & 31;
            uint2 hh, ll;
            split4h(pB[u], 1.0f, hh, ll);
            uint32_t off = SWZ256((uint32_t)(row * 256 + c4 * 8));
            *(uint2*)(st + PJ_BHI + off) = hh;
            *(uint2*)(st + PJ_BLO + off) = ll;
        }
        __syncthreads();

        if (c < 63) {
            int nb = (c + 1) * 64;
            #pragma unroll
            for (int u = 0; u < 2; u++) {
                int idx = tid + 512 * u;
                int row = idx >> 3, c8 = idx & 7;
                size_t o = (size_t)row * (Nn / 2) + (nb >> 1) + c8 * 4;
                pA[u]     = *(const uint4*)&PTh[o];
                pA[2 + u] = *(const uint4*)&PTl[o];
            }
            #pragma unroll
            for (int u = 0; u < 4; u++) {
                int idx = tid + 512 * u;
                int row = idx >> 5, c4 = idx & 31;
                pB[u] = *(const float4*)&X[(size_t)(nb + row) * Dn + c4 * 4];
            }
        }

        const uint32_t sA = sbase + (c & 1) * PJ_STAGE;
        const uint32_t sB = sA + PJ_BHI;
        #pragma unroll
        for (int ks = 0; ks < 4; ks++) {
            uint32_t ah[2][4], al[2][4];
            #pragma unroll
            for (int mi = 0; mi < 2; mi++) {
                uint32_t off = SWZ128((uint32_t)((warp_m + mi * 16 + (lane & 15)) * 128
                                                 + ks * 32 + (lane >> 4) * 16));
                LDSM4(ah[mi], sA + PJ_AHI + off);
                LDSM4(al[mi], sA + PJ_ALO + off);
            }
            #pragma unroll
            for (int g2 = 0; g2 < 2; g2++) {
                uint32_t offb = SWZ256((uint32_t)((ks * 16 + (lane & 15)) * 256
                                                  + warp_d * 2 + g2 * 32 + (lane >> 4) * 16));
                uint32_t bh[4], bl[4];
                LDSM4T(bh, sB + offb);
                LDSM4T(bl, sB + (PJ_BLO - PJ_BHI) + offb);
                #pragma unroll
                for (int mi = 0; mi < 2; mi++) {
                    #pragma unroll
                    for (int jj = 0; jj < 2; jj++) {
                        float* cc = acc[mi][g2 * 2 + jj];
                        MMA_F16(cc, ah[mi], bh[jj * 2], bh[jj * 2 + 1]);
                        MMA_F16(cc, ah[mi], bl[jj * 2], bl[jj * 2 + 1]);
                        MMA_F16(cc, al[mi], bh[jj * 2], bh[jj * 2 + 1]);
                    }
                }
            }
        }
        __syncthreads();
    }

    // ---- epilogue: split accumulators to fp16 limbs, store pairs ----
    #pragma unroll
    for (int mi = 0; mi < 2; mi++) {
        #pragma unroll
        for (int j = 0; j < 4; j++) {
            int row = warp_m + mi * 16 + (lane >> 2);
            int cp  = (warp_d + j * 8) / 2 + (lane & 3);   // u32 pair column
            float a0 = acc[mi][j][0], a1 = acc[mi][j][1];
            float a2 = acc[mi][j][2], a3 = acc[mi][j][3];
            uint32_t h0 = cvt2h(a1, a0);
            uint32_t l0 = cvt2h(a1 - f16hi(h0), a0 - f16lo(h0));
            uint32_t h1 = cvt2h(a3, a2);
            uint32_t l1 = cvt2h(a3 - f16hi(h1), a2 - f16lo(h1));
            Gh[(size_t)row * HD + cp]       = h0;
            Gl[(size_t)row * HD + cp]       = l0;
            Gh[(size_t)(row + 8) * HD + cp] = h1;
            Gl[(size_t)(row + 8) * HD + cp] = l1;
        }
    }
}

// ============================================================================
// Kernel 2: tensor-core attention; 1 tile (128 rows) per CTA (round-8 shape),
// K/V limbs copied directly from gmem (pre-split by proj epilogue).
// ============================================================================
#define AT_QHI  0
#define AT_QLO  16384
#define AT_PHI  0
#define AT_KHI  32768
#define AT_KLO  49152
#define AT_VHI  65536
#define AT_VLO  81920
#define AT_SMAX 98304
#define AT_SSUM 99328
#define AT_SMEM 100352

__global__ void __launch_bounds__(256, 2) attn_mma_kernel(
    const float* __restrict__ qg, float* __restrict__ outg)
{
    const int nt = blockIdx.x;
    const int h  = blockIdx.y;
    const int b  = blockIdx.z;

    extern __shared__ __align__(1024) unsigned char smb[];
    const uint32_t sbase = smem_u32(smb);
    float* smax = (float*)(smb + AT_SMAX);
    float* ssum = (float*)(smb + AT_SSUM);

    const int tid  = threadIdx.x;
    const int wid  = tid >> 5, lane = tid & 31;
    const int g    = lane >> 2, tk = lane & 3;
    const int wm   = (wid >> 1) * 32;
    const int kh   = wid & 1;

    // ---- K/V limb fill (direct 16B copies) + Q fill+split, one phase ----
    {
        const size_t kvb = (size_t)b * Kn * HD + h * 32;
        #pragma unroll
        for (int t = 0; t < 4; t++) {
            int idx = tid + 256 * t;
            int row = idx >> 3, u4 = idx & 7;
            size_t o = kvb + (size_t)row * HD + u4 * 4;
            uint32_t off = SWZ128((uint32_t)(row * 128 + u4 * 16));
            *(uint4*)(smb + AT_KHI + off) = *(const uint4*)&g_kph[o];
            *(uint4*)(smb + AT_KLO + off) = *(const uint4*)&g_kpl[o];
            *(uint4*)(smb + AT_VHI + off) = *(const uint4*)&g_vph[o];
            *(uint4*)(smb + AT_VLO + off) = *(const uint4*)&g_vpl[o];
        }
        const size_t qbase = ((size_t)b * Nn + (size_t)nt * 128) * Dn + h * 64;
        #pragma unroll
        for (int t = 0; t < 8; t++) {
            int idx = tid + 256 * t;
            int row = idx >> 4, c4 = idx & 15;
            size_t go = (size_t)row * Dn + c4 * 4;
            uint32_t off = SWZ128((uint32_t)(row * 128 + c4 * 8));
            uint2 hh, ll;
            split4h(*(const float4*)&qg[qbase + go], 0.125f, hh, ll);
            *(uint2*)(smb + AT_QHI + off) = hh;
            *(uint2*)(smb + AT_QLO + off) = ll;
        }
    }
    __syncthreads();

    // ---- GEMM1: dots[128n x 128k]; warp tile 32n x 64k; 3-pass ----
    float acc[2][8][4];
    #pragma unroll
    for (int i = 0; i < 2; i++)
        #pragma unroll
        for (int j = 0; j < 8; j++)
            #pragma unroll
            for (int q = 0; q < 4; q++) acc[i][j][q] = 0.0f;

    {
        const int wk = kh * 64;
        #pragma unroll
        for (int ks = 0; ks < 4; ks++) {
            uint32_t ah[2][4], al[2][4];
            #pragma unroll
            for (int mi = 0; mi < 2; mi++) {
                uint32_t off = SWZ128((uint32_t)((wm + mi * 16 + (lane & 15)) * 128
                                                 + ks * 32 + (lane >> 4) * 16));
                LDSM4(ah[mi], sbase + AT_QHI + off);
                LDSM4(al[mi], sbase + AT_QLO + off);
            }
            #pragma unroll
            for (int jj = 0; jj < 4; jj++) {
                uint32_t offb = SWZ128((uint32_t)((wk + jj * 16 + (lane & 15)) * 128
                                                  + ks * 32 + (lane >> 4) * 16));
                uint32_t bh[4], bl[4];
                LDSM4(bh, sbase + AT_KHI + offb);
                LDSM4(bl, sbase + AT_KLO + offb);
                // non-trans B pairing: tile(2jj)=(r0,r2), tile(2jj+1)=(r1,r3)
                #pragma unroll
                for (int mi = 0; mi < 2; mi++) {
                    float* c0 = acc[mi][jj * 2];
                    MMA_F16(c0, ah[mi], bh[0], bh[2]);
                    MMA_F16(c0, ah[mi], bl[0], bl[2]);
                    MMA_F16(c0, al[mi], bh[0], bh[2]);
                    float* c1v = acc[mi][jj * 2 + 1];
                    MMA_F16(c1v, ah[mi], bh[1], bh[3]);
                    MMA_F16(c1v, ah[mi], bl[1], bl[3]);
                    MMA_F16(c1v, al[mi], bh[1], bh[3]);
                }
            }
        }
    }

    // ---- softmax part 1: row max ----
    #pragma unroll
    for (int mi = 0; mi < 2; mi++) {
        #pragma unroll
        for (int h2 = 0; h2 < 2; h2++) {
            float m = acc[mi][0][h2 * 2];
            #pragma unroll
            for (int j = 0; j < 8; j++)
                m = fmaxf(m, fmaxf(acc[mi][j][h2 * 2], acc[mi][j][h2 * 2 + 1]));
            m = fmaxf(m, __shfl_xor_sync(0xffffffffu, m, 1));
            m = fmaxf(m, __shfl_xor_sync(0xffffffffu, m, 2));
            if (tk == 0) smax[(wm + mi * 16 + g + h2 * 8) * 2 + kh] = m;
        }
    }
    __syncthreads();

    // ---- softmax part 2: exp, write SINGLE fp16 P (dead Q region);
    //      accumulate rowsum from the ROUNDED P ----
    #pragma unroll
    for (int mi = 0; mi < 2; mi++) {
        #pragma unroll
        for (int h2 = 0; h2 < 2; h2++) {
            int row = wm + mi * 16 + g + h2 * 8;
            float M = fmaxf(smax[row * 2], smax[row * 2 + 1]);
            float s = 0.0f;
            #pragma unroll
            for (int j = 0; j < 8; j++) {
                float x0 = __expf(acc[mi][j][h2 * 2]     - M);
                float x1 = __expf(acc[mi][j][h2 * 2 + 1] - M);
                uint32_t ph = cvt2h(x1, x0);
                s += f16lo(ph) + f16hi(ph);
                uint32_t off = SWZ256((uint32_t)(row * 256 + kh * 128 + j * 16 + tk * 4));
                *(uint32_t*)(smb + AT_PHI + off) = ph;
            }
            s += __shfl_xor_sync(0xffffffffu, s, 1);
            s += __shfl_xor_sync(0xffffffffu, s, 2);
            if (tk == 0) ssum[row * 2 + kh] = s;
        }
    }
    __syncthreads();

    // ---- GEMM2: out = P . VV; 2-pass (P single, V 2-limb) ----
    float o[2][4][4];
    #pragma unroll
    for (int i = 0; i < 2; i++)
        #pragma unroll
        for (int j = 0; j < 4; j++)
            #pragma unroll
            for (int q = 0; q < 4; q++) o[i][j][q] = 0.0f;

    {
        const int wdh = kh * 32;
        #pragma unroll
        for (int ks = 0; ks < 8; ks++) {
            uint32_t ah[2][4];
            #pragma unroll
            for (int mi = 0; mi < 2; mi++) {
                uint32_t off = SWZ256((uint32_t)((wm + mi * 16 + (lane & 15)) * 256
                                                 + ks * 32 + (lane >> 4) * 16));
                LDSM4(ah[mi], sbase + AT_PHI + off);
            }
            #pragma unroll
            for (int g2 = 0; g2 < 2; g2++) {
                uint32_t offb = SWZ128((uint32_t)((ks * 16 + (lane & 15)) * 128
                                                  + wdh * 2 + g2 * 32 + (lane >> 4) * 16));
                uint32_t bh[4], bl[4];
                LDSM4T(bh, sbase + AT_VHI + offb);
                LDSM4T(bl, sbase + AT_VLO + offb);
                // trans B pairing: tile(g2*2)=(r0,r1), tile(g2*2+1)=(r2,r3)
                #pragma unroll
                for (int mi = 0; mi < 2; mi++) {
                    #pragma unroll
                    for (int jj = 0; jj < 2; jj++) {
                        float* cc = o[mi][g2 * 2 + jj];
                        MMA_F16(cc, ah[mi], bh[jj * 2], bh[jj * 2 + 1]);
                        MMA_F16(cc, ah[mi], bl[jj * 2], bl[jj * 2 + 1]);
                    }
                }
            }
        }
    }

    // ---- epilogue: normalize by 1/rowsum, store ----
    {
        const int wdh = kh * 32;
        const size_t obase = ((size_t)b * Nn + (size_t)nt * 128) * Dn + h * 64;
        #pragma unroll
        for (int mi = 0; mi < 2; mi++) {
            int r0 = wm + mi * 16 + g;
            int r1 = r0 + 8;
            float ri0 = 1.0f / (ssum[r0 * 2] + ssum[r0 * 2 + 1]);
            float ri1 = 1.0f / (ssum[r1 * 2] + ssum[r1 * 2 + 1]);
            #pragma unroll
            for (int j = 0; j < 4; j++) {
                int col = wdh + j * 8 + tk * 2;
                *(float2*)&outg[obase + (size_t)r0 * Dn + col] =
                    make_float2(o[mi][j][0] * ri0, o[mi][j][1] * ri0);
                *(float2*)&outg[obase + (size_t)r1 * Dn + col] =
                    make_float2(o[mi][j][2] * ri1, o[mi][j][3] * ri1);
            }
        }
    }
}

// ============================================================================
// Launch
// ============================================================================
extern "C" void kernel_launch(void* const* d_in, const int* in_sizes, int n_in,
                              void* d_out, int out_size)
{
    const float* q      = (const float*)d_in[0];
    const float* keys   = (const float*)d_in[1];
    const float* values = (const float*)d_in[2];
    const float* pk     = (const float*)d_in[3];
    const float* pv     = (const float*)d_in[4];
    float* out = (float*)d_out;

    cudaFuncSetAttribute(proj_mma_kernel,
                         cudaFuncAttributeMaxDynamicSharedMemorySize, PJ_SMEM);
    cudaFuncSetAttribute(attn_mma_kernel,
                         cudaFuncAttributeMaxDynamicSharedMemorySize, AT_SMEM);

    ptrans_kernel<<<dim3(Nn / 32, 2), 256>>>(pk, pv);
    proj_mma_kernel<<<dim3(8, Bsz, 2), 512, PJ_SMEM>>>(keys, values);
    attn_mma_kernel<<<dim3(Nn / 128, Hn, Bsz), 256, AT_SMEM>>>(q, out);
}

// round 12
// speedup vs baseline: 1.0212x; 1.0074x over previous
#include <cuda_runtime.h>
#include <cuda_fp16.h>
#include <cstdint>
#include <cstddef>

// Problem constants
#define Bsz 8
#define Hn  16
#define Nn  4096
#define DHn 64
#define Kn  128
#define Dn  1024
#define HD  (Dn / 2)     // u32 (fp16-pair) row stride

// Device scratch (no allocs allowed)
__device__ uint32_t g_kph[Bsz * Kn * HD];          // projected K hi limb (fp16 pairs)
__device__ uint32_t g_kpl[Bsz * Kn * HD];          // projected K lo limb
__device__ uint32_t g_vph[Bsz * Kn * HD];          // projected V hi limb
__device__ uint32_t g_vpl[Bsz * Kn * HD];          // projected V lo limb
__device__ uint32_t g_PTh[2 * Kn * (Nn / 2)];      // P^T hi f16 pairs [w][k][n/2]
__device__ uint32_t g_PTl[2 * Kn * (Nn / 2)];      // P^T lo f16 pairs

typedef unsigned long long u64;

// ---------------------------------------------------------------------------
// helpers (fp16 limbs)
// ---------------------------------------------------------------------------
__device__ __forceinline__ uint32_t cvt2h(float hi_elem, float lo_elem) {
    uint32_t r;
    asm("cvt.rn.f16x2.f32 %0, %1, %2;" : "=r"(r) : "f"(hi_elem), "f"(lo_elem));
    return r;
}
__device__ __forceinline__ float f16lo(uint32_t p) {
    return __half2float(__ushort_as_half((unsigned short)(p & 0xffffu)));
}
__device__ __forceinline__ float f16hi(uint32_t p) {
    return __half2float(__ushort_as_half((unsigned short)(p >> 16)));
}

#define SWZ128(x) ((x) ^ (((x) >> 3) & 0x70))
#define SWZ256(x) ((x) ^ (((x) >> 4) & 0x70))

#define LDSM4(r, a) \
    asm volatile("ldmatrix.sync.aligned.m8n8.x4.shared.b16 {%0,%1,%2,%3}, [%4];" \
        : "=r"((r)[0]), "=r"((r)[1]), "=r"((r)[2]), "=r"((r)[3]) : "r"(a))
#define LDSM4T(r, a) \
    asm volatile("ldmatrix.sync.aligned.m8n8.x4.trans.shared.b16 {%0,%1,%2,%3}, [%4];" \
        : "=r"((r)[0]), "=r"((r)[1]), "=r"((r)[2]), "=r"((r)[3]) : "r"(a))
#define MMA_F16(c, a, b0v, b1v) \
    asm volatile("mma.sync.aligned.m16n8k16.row.col.f32.f16.f16.f32 " \
        "{%0,%1,%2,%3}, {%4,%5,%6,%7}, {%8,%9}, {%0,%1,%2,%3};" \
        : "+f"((c)[0]), "+f"((c)[1]), "+f"((c)[2]), "+f"((c)[3]) \
        : "r"((a)[0]), "r"((a)[1]), "r"((a)[2]), "r"((a)[3]), "r"(b0v), "r"(b1v))

// 64-thread named barrier for a warp pair (ids 1..4)
#define BAR_PAIR(id) asm volatile("bar.sync %0, 64;" :: "r"(id) : "memory")

__device__ __forceinline__ uint32_t smem_u32(const void* p) {
    uint32_t a;
    asm("{ .reg .u64 t; cvta.to.shared.u64 t, %1; cvt.u32.u64 %0, t; }" : "=r"(a) : "l"(p));
    return a;
}

// split a float4 (optionally scaled) into hi/lo f16x2 pairs
__device__ __forceinline__ void split4h(float4 v, float s, uint2& h, uint2& l) {
    v.x *= s; v.y *= s; v.z *= s; v.w *= s;
    uint32_t h01 = cvt2h(v.y, v.x);
    uint32_t h23 = cvt2h(v.w, v.z);
    float h0 = f16lo(h01), h1 = f16hi(h01);
    float h2 = f16lo(h23), h3 = f16hi(h23);
    uint32_t l01 = cvt2h(v.y - h1, v.x - h0);
    uint32_t l23 = cvt2h(v.w - h3, v.z - h2);
    h = make_uint2(h01, h23);
    l = make_uint2(l01, l23);
}

// ============================================================================
// Kernel 0: transpose P [4096 n][128 k] -> split-f16 PT [w][128 k][4096 n]
// ============================================================================
__global__ void __launch_bounds__(256) ptrans_kernel(
    const float* __restrict__ pk, const float* __restrict__ pv)
{
    __shared__ float sT[128][33];
    const int t  = threadIdx.x;
    const int n0 = blockIdx.x * 32;
    const int w  = blockIdx.y;
    const float* __restrict__ P = w ? pv : pk;

    #pragma unroll
    for (int i = 0; i < 16; i++) {
        int idx = t + 256 * i;
        int r = idx >> 7, c = idx & 127;
        sT[c][r] = P[(size_t)(n0 + r) * Kn + c];
    }
    __syncthreads();

    uint32_t* __restrict__ oh = g_PTh + (size_t)w * Kn * (Nn / 2);
    uint32_t* __restrict__ ol = g_PTl + (size_t)w * Kn * (Nn / 2);
    #pragma unroll
    for (int i = 0; i < 8; i++) {
        int idx = t + 256 * i;
        int k = idx >> 4, pr = idx & 15;
        float x0 = sT[k][2 * pr], x1 = sT[k][2 * pr + 1];
        uint32_t h = cvt2h(x1, x0);
        float h0 = f16lo(h), h1 = f16hi(h);
        uint32_t l = cvt2h(x1 - h1, x0 - h0);
        size_t o = (size_t)k * (Nn / 2) + (n0 >> 1) + pr;
        oh[o] = h;
        ol[o] = l;
    }
}

// ============================================================================
// Kernel 1: mma.sync f16-split projection (3-pass); epilogue emits fp16 limbs
// ============================================================================
#define PJ_AHI 0
#define PJ_ALO 16384
#define PJ_BHI 32768
#define PJ_BLO 49152
#define PJ_STAGE 65536
#define PJ_SMEM (2 * PJ_STAGE)

__global__ void __launch_bounds__(512, 1) proj_mma_kernel(
    const float* __restrict__ keys, const float* __restrict__ values)
{
    const int dt = blockIdx.x;
    const int b  = blockIdx.y;
    const int w  = blockIdx.z;

    const float* __restrict__ X = (w ? values : keys) + (size_t)b * Nn * Dn + dt * 128;
    const uint32_t* __restrict__ PTh = g_PTh + (size_t)w * Kn * (Nn / 2);
    const uint32_t* __restrict__ PTl = g_PTl + (size_t)w * Kn * (Nn / 2);
    uint32_t* __restrict__ Gh = (w ? g_vph : g_kph) + (size_t)b * Kn * HD + dt * 64;
    uint32_t* __restrict__ Gl = (w ? g_vpl : g_kpl) + (size_t)b * Kn * HD + dt * 64;

    extern __shared__ __align__(1024) unsigned char dsm[];
    const uint32_t sbase = smem_u32(dsm);

    const int tid  = threadIdx.x;
    const int wid  = tid >> 5, lane = tid & 31;
    const int warp_m = (wid >> 2) * 32;
    const int warp_d = (wid & 3) * 32;

    float acc[2][4][4];
    #pragma unroll
    for (int i = 0; i < 2; i++)
        #pragma unroll
        for (int j = 0; j < 4; j++)
            #pragma unroll
            for (int q = 0; q < 4; q++) acc[i][j][q] = 0.0f;

    uint4  pA[4];
    float4 pB[4];

    #pragma unroll
    for (int u = 0; u < 2; u++) {
        int idx = tid + 512 * u;
        int row = idx >> 3, c8 = idx & 7;
        size_t o = (size_t)row * (Nn / 2) + c8 * 4;
        pA[u]     = *(const uint4*)&PTh[o];
        pA[2 + u] = *(const uint4*)&PTl[o];
    }
    #pragma unroll
    for (int u = 0; u < 4; u++) {
        int idx = tid + 512 * u;
        int row = idx >> 5, c4 = idx & 31;
        pB[u] = *(const float4*)&X[(size_t)row * Dn + c4 * 4];
    }

    for (int c = 0; c < 64; ++c) {
        unsigned char* st = dsm + (c & 1) * PJ_STAGE;

        #pragma unroll
        for (int u = 0; u < 2; u++) {
            int idx = tid + 512 * u;
            int row = idx >> 3, c8 = idx & 7;
            uint32_t off = SWZ128((uint32_t)(row * 128 + c8 * 16));
            *(uint4*)(st + PJ_AHI + off) = pA[u];
            *(uint4*)(st + PJ_ALO + off) = pA[2 + u];
        }
        #pragma unroll
        for (int u = 0; u < 4; u++) {
            int idx = tid + 512 * u;
            int row = idx >> 5, c4 = idx & 31;
            uint2 hh, ll;
            split4h(pB[u], 1.0f, hh, ll);
            uint32_t off = SWZ256((uint32_t)(row * 256 + c4 * 8));
            *(uint2*)(st + PJ_BHI + off) = hh;
            *(uint2*)(st + PJ_BLO + off) = ll;
        }
        __syncthreads();

        if (c < 63) {
            int nb = (c + 1) * 64;
            #pragma unroll
            for (int u = 0; u < 2; u++) {
                int idx = tid + 512 * u;
                int row = idx >> 3, c8 = idx & 7;
                size_t o = (size_t)row * (Nn / 2) + (nb >> 1) + c8 * 4;
                pA[u]     = *(const uint4*)&PTh[o];
                pA[2 + u] = *(const uint4*)&PTl[o];
            }
            #pragma unroll
            for (int u = 0; u < 4; u++) {
                int idx = tid + 512 * u;
                int row = idx >> 5, c4 = idx & 31;
                pB[u] = *(const float4*)&X[(size_t)(nb + row) * Dn + c4 * 4];
            }
        }

        const uint32_t sA = sbase + (c & 1) * PJ_STAGE;
        const uint32_t sB = sA + PJ_BHI;
        #pragma unroll
        for (int ks = 0; ks < 4; ks++) {
            uint32_t ah[2][4], al[2][4];
            #pragma unroll
            for (int mi = 0; mi < 2; mi++) {
                uint32_t off = SWZ128((uint32_t)((warp_m + mi * 16 + (lane & 15)) * 128
                                                 + ks * 32 + (lane >> 4) * 16));
                LDSM4(ah[mi], sA + PJ_AHI + off);
                LDSM4(al[mi], sA + PJ_ALO + off);
            }
            #pragma unroll
            for (int g2 = 0; g2 < 2; g2++) {
                uint32_t offb = SWZ256((uint32_t)((ks * 16 + (lane & 15)) * 256
                                                  + warp_d * 2 + g2 * 32 + (lane >> 4) * 16));
                uint32_t bh[4], bl[4];
                LDSM4T(bh, sB + offb);
                LDSM4T(bl, sB + (PJ_BLO - PJ_BHI) + offb);
                #pragma unroll
                for (int mi = 0; mi < 2; mi++) {
                    #pragma unroll
                    for (int jj = 0; jj < 2; jj++) {
                        float* cc = acc[mi][g2 * 2 + jj];
                        MMA_F16(cc, ah[mi], bh[jj * 2], bh[jj * 2 + 1]);
                        MMA_F16(cc, ah[mi], bl[jj * 2], bl[jj * 2 + 1]);
                        MMA_F16(cc, al[mi], bh[jj * 2], bh[jj * 2 + 1]);
                    }
                }
            }
        }
        __syncthreads();
    }

    // ---- epilogue: split accumulators to fp16 limbs, store pairs ----
    #pragma unroll
    for (int mi = 0; mi < 2; mi++) {
        #pragma unroll
        for (int j = 0; j < 4; j++) {
            int row = warp_m + mi * 16 + (lane >> 2);
            int cp  = (warp_d + j * 8) / 2 + (lane & 3);   // u32 pair column
            float a0 = acc[mi][j][0], a1 = acc[mi][j][1];
            float a2 = acc[mi][j][2], a3 = acc[mi][j][3];
            uint32_t h0 = cvt2h(a1, a0);
            uint32_t l0 = cvt2h(a1 - f16hi(h0), a0 - f16lo(h0));
            uint32_t h1 = cvt2h(a3, a2);
            uint32_t l1 = cvt2h(a3 - f16hi(h1), a2 - f16lo(h1));
            Gh[(size_t)row * HD + cp]       = h0;
            Gl[(size_t)row * HD + cp]       = l0;
            Gh[(size_t)(row + 8) * HD + cp] = h1;
            Gl[(size_t)(row + 8) * HD + cp] = l1;
        }
    }
}

// ============================================================================
// Kernel 2: tensor-core attention; 1 tile per CTA; warp-pair decoupling.
//   P stored split by k-half at 128 B/row into QHI (k 0..63) / QLO (k 64..127):
//   P row r overlays exactly Q row r, which only the owning warp pair reads
//   => softmax barriers are 64-thread named barriers, not CTA-wide.
// ============================================================================
#define AT_QHI  0
#define AT_QLO  16384
#define AT_KHI  32768
#define AT_KLO  49152
#define AT_VHI  65536
#define AT_VLO  81920
#define AT_SMAX 98304
#define AT_SSUM 99328
#define AT_SMEM 100352

__global__ void __launch_bounds__(256, 2) attn_mma_kernel(
    const float* __restrict__ qg, float* __restrict__ outg)
{
    const int nt = blockIdx.x;
    const int h  = blockIdx.y;
    const int b  = blockIdx.z;

    extern __shared__ __align__(1024) unsigned char smb[];
    const uint32_t sbase = smem_u32(smb);
    float* smax = (float*)(smb + AT_SMAX);
    float* ssum = (float*)(smb + AT_SSUM);

    const int tid  = threadIdx.x;
    const int wid  = tid >> 5, lane = tid & 31;
    const int g    = lane >> 2, tk = lane & 3;
    const int wm   = (wid >> 1) * 32;
    const int kh   = wid & 1;
    const int barid = 1 + (wid >> 1);     // named barrier per warp pair

    // ---- K/V limb fill (direct 16B copies) + Q fill+split, one phase ----
    {
        const size_t kvb = (size_t)b * Kn * HD + h * 32;
        #pragma unroll
        for (int t = 0; t < 4; t++) {
            int idx = tid + 256 * t;
            int row = idx >> 3, u4 = idx & 7;
            size_t o = kvb + (size_t)row * HD + u4 * 4;
            uint32_t off = SWZ128((uint32_t)(row * 128 + u4 * 16));
            *(uint4*)(smb + AT_KHI + off) = *(const uint4*)&g_kph[o];
            *(uint4*)(smb + AT_KLO + off) = *(const uint4*)&g_kpl[o];
            *(uint4*)(smb + AT_VHI + off) = *(const uint4*)&g_vph[o];
            *(uint4*)(smb + AT_VLO + off) = *(const uint4*)&g_vpl[o];
        }
        const size_t qbase = ((size_t)b * Nn + (size_t)nt * 128) * Dn + h * 64;
        #pragma unroll
        for (int t = 0; t < 8; t++) {
            int idx = tid + 256 * t;
            int row = idx >> 4, c4 = idx & 15;
            size_t go = (size_t)row * Dn + c4 * 4;
            uint32_t off = SWZ128((uint32_t)(row * 128 + c4 * 8));
            uint2 hh, ll;
            split4h(*(const float4*)&qg[qbase + go], 0.125f, hh, ll);
            *(uint2*)(smb + AT_QHI + off) = hh;
            *(uint2*)(smb + AT_QLO + off) = ll;
        }
    }
    __syncthreads();   // only CTA-wide barrier: striped loads -> per-pair reads

    // ---- GEMM1: dots[128n x 128k]; warp tile 32n x 64k; 3-pass ----
    float acc[2][8][4];
    #pragma unroll
    for (int i = 0; i < 2; i++)
        #pragma unroll
        for (int j = 0; j < 8; j++)
            #pragma unroll
            for (int q = 0; q < 4; q++) acc[i][j][q] = 0.0f;

    {
        const int wk = kh * 64;
        #pragma unroll
        for (int ks = 0; ks < 4; ks++) {
            uint32_t ah[2][4], al[2][4];
            #pragma unroll
            for (int mi = 0; mi < 2; mi++) {
                uint32_t off = SWZ128((uint32_t)((wm + mi * 16 + (lane & 15)) * 128
                                                 + ks * 32 + (lane >> 4) * 16));
                LDSM4(ah[mi], sbase + AT_QHI + off);
                LDSM4(al[mi], sbase + AT_QLO + off);
            }
            #pragma unroll
            for (int jj = 0; jj < 4; jj++) {
                uint32_t offb = SWZ128((uint32_t)((wk + jj * 16 + (lane & 15)) * 128
                                                  + ks * 32 + (lane >> 4) * 16));
                uint32_t bh[4], bl[4];
                LDSM4(bh, sbase + AT_KHI + offb);
                LDSM4(bl, sbase + AT_KLO + offb);
                // non-trans B pairing: tile(2jj)=(r0,r2), tile(2jj+1)=(r1,r3)
                #pragma unroll
                for (int mi = 0; mi < 2; mi++) {
                    float* c0 = acc[mi][jj * 2];
                    MMA_F16(c0, ah[mi], bh[0], bh[2]);
                    MMA_F16(c0, ah[mi], bl[0], bl[2]);
                    MMA_F16(c0, al[mi], bh[0], bh[2]);
                    float* c1v = acc[mi][jj * 2 + 1];
                    MMA_F16(c1v, ah[mi], bh[1], bh[3]);
                    MMA_F16(c1v, ah[mi], bl[1], bl[3]);
                    MMA_F16(c1v, al[mi], bh[1], bh[3]);
                }
            }
        }
    }

    // ---- softmax part 1: row max (pair-local) ----
    #pragma unroll
    for (int mi = 0; mi < 2; mi++) {
        #pragma unroll
        for (int h2 = 0; h2 < 2; h2++) {
            float m = acc[mi][0][h2 * 2];
            #pragma unroll
            for (int j = 0; j < 8; j++)
                m = fmaxf(m, fmaxf(acc[mi][j][h2 * 2], acc[mi][j][h2 * 2 + 1]));
            m = fmaxf(m, __shfl_xor_sync(0xffffffffu, m, 1));
            m = fmaxf(m, __shfl_xor_sync(0xffffffffu, m, 2));
            if (tk == 0) smax[(wm + mi * 16 + g + h2 * 8) * 2 + kh] = m;
        }
    }
    BAR_PAIR(barid);

    // ---- softmax part 2: exp, write P (own k-half region, 128 B rows);
    //      accumulate rowsum from the ROUNDED P.
    //      NOTE: store via GENERIC pointer (smb), not the cvta'd sbase. ----
    {
        unsigned char* pptr = smb + (kh ? AT_QLO : AT_QHI);
        #pragma unroll
        for (int mi = 0; mi < 2; mi++) {
            #pragma unroll
            for (int h2 = 0; h2 < 2; h2++) {
                int row = wm + mi * 16 + g + h2 * 8;
                float M = fmaxf(smax[row * 2], smax[row * 2 + 1]);
                float s = 0.0f;
                #pragma unroll
                for (int j = 0; j < 8; j++) {
                    float x0 = __expf(acc[mi][j][h2 * 2]     - M);
                    float x1 = __expf(acc[mi][j][h2 * 2 + 1] - M);
                    uint32_t ph = cvt2h(x1, x0);
                    s += f16lo(ph) + f16hi(ph);
                    uint32_t off = SWZ128((uint32_t)(row * 128 + j * 16 + tk * 4));
                    *(uint32_t*)(pptr + off) = ph;
                }
                s += __shfl_xor_sync(0xffffffffu, s, 1);
                s += __shfl_xor_sync(0xffffffffu, s, 2);
                if (tk == 0) ssum[row * 2 + kh] = s;
            }
        }
    }
    BAR_PAIR(barid);

    // ---- GEMM2: out = P . VV; 2-pass (P single, V 2-limb) ----
    float o[2][4][4];
    #pragma unroll
    for (int i = 0; i < 2; i++)
        #pragma unroll
        for (int j = 0; j < 4; j++)
            #pragma unroll
            for (int q = 0; q < 4; q++) o[i][j][q] = 0.0f;

    {
        const int wdh = kh * 32;
        #pragma unroll
        for (int ks = 0; ks < 8; ks++) {
            const uint32_t pbase = sbase + (ks < 4 ? AT_QHI : AT_QLO);
            uint32_t ah[2][4];
            #pragma unroll
            for (int mi = 0; mi < 2; mi++) {
                uint32_t off = SWZ128((uint32_t)((wm + mi * 16 + (lane & 15)) * 128
                                                 + (ks & 3) * 32 + (lane >> 4) * 16));
                LDSM4(ah[mi], pbase + off);
            }
            #pragma unroll
            for (int g2 = 0; g2 < 2; g2++) {
                uint32_t offb = SWZ128((uint32_t)((ks * 16 + (lane & 15)) * 128
                                                  + wdh * 2 + g2 * 32 + (lane >> 4) * 16));
                uint32_t bh[4], bl[4];
                LDSM4T(bh, sbase + AT_VHI + offb);
                LDSM4T(bl, sbase + AT_VLO + offb);
                // trans B pairing: tile(g2*2)=(r0,r1), tile(g2*2+1)=(r2,r3)
                #pragma unroll
                for (int mi = 0; mi < 2; mi++) {
                    #pragma unroll
                    for (int jj = 0; jj < 2; jj++) {
                        float* cc = o[mi][g2 * 2 + jj];
                        MMA_F16(cc, ah[mi], bh[jj * 2], bh[jj * 2 + 1]);
                        MMA_F16(cc, ah[mi], bl[jj * 2], bl[jj * 2 + 1]);
                    }
                }
            }
        }
    }

    // ---- epilogue: normalize by 1/rowsum, store ----
    {
        const int wdh = kh * 32;
        const size_t obase = ((size_t)b * Nn + (size_t)nt * 128) * Dn + h * 64;
        #pragma unroll
        for (int mi = 0; mi < 2; mi++) {
            int r0 = wm + mi * 16 + g;
            int r1 = r0 + 8;
            float ri0 = 1.0f / (ssum[r0 * 2] + ssum[r0 * 2 + 1]);
            float ri1 = 1.0f / (ssum[r1 * 2] + ssum[r1 * 2 + 1]);
            #pragma unroll
            for (int j = 0; j < 4; j++) {
                int col = wdh + j * 8 + tk * 2;
                *(float2*)&outg[obase + (size_t)r0 * Dn + col] =
                    make_float2(o[mi][j][0] * ri0, o[mi][j][1] * ri0);
                *(float2*)&outg[obase + (size_t)r1 * Dn + col] =
                    make_float2(o[mi][j][2] * ri1, o[mi][j][3] * ri1);
            }
        }
    }
}

// ============================================================================
// Launch
// ============================================================================
extern "C" void kernel_launch(void* const* d_in, const int* in_sizes, int n_in,
                              void* d_out, int out_size)
{
    const float* q      = (const float*)d_in[0];
    const float* keys   = (const float*)d_in[1];
    const float* values = (const float*)d_in[2];
    const float* pk     = (const float*)d_in[3];
    const float* pv     = (const float*)d_in[4];
    float* out = (float*)d_out;

    cudaFuncSetAttribute(proj_mma_kernel,
                         cudaFuncAttributeMaxDynamicSharedMemorySize, PJ_SMEM);
    cudaFuncSetAttribute(attn_mma_kernel,
                         cudaFuncAttributeMaxDynamicSharedMemorySize, AT_SMEM);

    ptrans_kernel<<<dim3(Nn / 32, 2), 256>>>(pk, pv);
    proj_mma_kernel<<<dim3(8, Bsz, 2), 512, PJ_SMEM>>>(keys, values);
    attn_mma_kernel<<<dim3(Nn / 128, Hn, Bsz), 256, AT_SMEM>>>(q, out);
}

// round 13
// speedup vs baseline: 1.0763x; 1.0539x over previous
#include <cuda_runtime.h>
#include <cuda_fp16.h>
#include <cstdint>
#include <cstddef>

// Problem constants
#define Bsz 8
#define Hn  16
#define Nn  4096
#define DHn 64
#define Kn  128
#define Dn  1024
#define HD  (Dn / 2)     // u32 (fp16-pair) row stride

// Device scratch (no allocs allowed)
__device__ uint32_t g_kph[Bsz * Kn * HD];          // projected K hi limb (fp16 pairs)
__device__ uint32_t g_kpl[Bsz * Kn * HD];          // projected K lo limb (unused by attn now)
__device__ uint32_t g_vph[Bsz * Kn * HD];          // projected V hi limb
__device__ uint32_t g_vpl[Bsz * Kn * HD];          // projected V lo limb
__device__ uint32_t g_PTh[2 * Kn * (Nn / 2)];      // P^T hi f16 pairs [w][k][n/2]
__device__ uint32_t g_PTl[2 * Kn * (Nn / 2)];      // P^T lo f16 pairs

typedef unsigned long long u64;

// ---------------------------------------------------------------------------
// helpers (fp16 limbs)
// ---------------------------------------------------------------------------
__device__ __forceinline__ uint32_t cvt2h(float hi_elem, float lo_elem) {
    uint32_t r;
    asm("cvt.rn.f16x2.f32 %0, %1, %2;" : "=r"(r) : "f"(hi_elem), "f"(lo_elem));
    return r;
}
__device__ __forceinline__ float f16lo(uint32_t p) {
    return __half2float(__ushort_as_half((unsigned short)(p & 0xffffu)));
}
__device__ __forceinline__ float f16hi(uint32_t p) {
    return __half2float(__ushort_as_half((unsigned short)(p >> 16)));
}

#define SWZ128(x) ((x) ^ (((x) >> 3) & 0x70))
#define SWZ256(x) ((x) ^ (((x) >> 4) & 0x70))

#define LDSM4(r, a) \
    asm volatile("ldmatrix.sync.aligned.m8n8.x4.shared.b16 {%0,%1,%2,%3}, [%4];" \
        : "=r"((r)[0]), "=r"((r)[1]), "=r"((r)[2]), "=r"((r)[3]) : "r"(a))
#define LDSM4T(r, a) \
    asm volatile("ldmatrix.sync.aligned.m8n8.x4.trans.shared.b16 {%0,%1,%2,%3}, [%4];" \
        : "=r"((r)[0]), "=r"((r)[1]), "=r"((r)[2]), "=r"((r)[3]) : "r"(a))
#define MMA_F16(c, a, b0v, b1v) \
    asm volatile("mma.sync.aligned.m16n8k16.row.col.f32.f16.f16.f32 " \
        "{%0,%1,%2,%3}, {%4,%5,%6,%7}, {%8,%9}, {%0,%1,%2,%3};" \
        : "+f"((c)[0]), "+f"((c)[1]), "+f"((c)[2]), "+f"((c)[3]) \
        : "r"((a)[0]), "r"((a)[1]), "r"((a)[2]), "r"((a)[3]), "r"(b0v), "r"(b1v))

// 64-thread named barrier for a warp pair (ids 1..4)
#define BAR_PAIR(id) asm volatile("bar.sync %0, 64;" :: "r"(id) : "memory")

__device__ __forceinline__ uint32_t smem_u32(const void* p) {
    uint32_t a;
    asm("{ .reg .u64 t; cvta.to.shared.u64 t, %1; cvt.u32.u64 %0, t; }" : "=r"(a) : "l"(p));
    return a;
}

// split a float4 (optionally scaled) into hi/lo f16x2 pairs
__device__ __forceinline__ void split4h(float4 v, float s, uint2& h, uint2& l) {
    v.x *= s; v.y *= s; v.z *= s; v.w *= s;
    uint32_t h01 = cvt2h(v.y, v.x);
    uint32_t h23 = cvt2h(v.w, v.z);
    float h0 = f16lo(h01), h1 = f16hi(h01);
    float h2 = f16lo(h23), h3 = f16hi(h23);
    uint32_t l01 = cvt2h(v.y - h1, v.x - h0);
    uint32_t l23 = cvt2h(v.w - h3, v.z - h2);
    h = make_uint2(h01, h23);
    l = make_uint2(l01, l23);
}

// ============================================================================
// Kernel 0: transpose P [4096 n][128 k] -> split-f16 PT [w][128 k][4096 n]
// ============================================================================
__global__ void __launch_bounds__(256) ptrans_kernel(
    const float* __restrict__ pk, const float* __restrict__ pv)
{
    __shared__ float sT[128][33];
    const int t  = threadIdx.x;
    const int n0 = blockIdx.x * 32;
    const int w  = blockIdx.y;
    const float* __restrict__ P = w ? pv : pk;

    #pragma unroll
    for (int i = 0; i < 16; i++) {
        int idx = t + 256 * i;
        int r = idx >> 7, c = idx & 127;
        sT[c][r] = P[(size_t)(n0 + r) * Kn + c];
    }
    __syncthreads();

    uint32_t* __restrict__ oh = g_PTh + (size_t)w * Kn * (Nn / 2);
    uint32_t* __restrict__ ol = g_PTl + (size_t)w * Kn * (Nn / 2);
    #pragma unroll
    for (int i = 0; i < 8; i++) {
        int idx = t + 256 * i;
        int k = idx >> 4, pr = idx & 15;
        float x0 = sT[k][2 * pr], x1 = sT[k][2 * pr + 1];
        uint32_t h = cvt2h(x1, x0);
        float h0 = f16lo(h), h1 = f16hi(h);
        uint32_t l = cvt2h(x1 - h1, x0 - h0);
        size_t o = (size_t)k * (Nn / 2) + (n0 >> 1) + pr;
        oh[o] = h;
        ol[o] = l;
    }
}

// ============================================================================
// Kernel 1: mma.sync f16-split projection.
//   K (w=0): 3-pass (error lands in softmax exponent — keep tight)
//   V (w=1): 2-pass, P exact x X_hi (drop ah*bl) — output-relative error only
//   Epilogue emits fp16 limbs.
// ============================================================================
#define PJ_AHI 0
#define PJ_ALO 16384
#define PJ_BHI 32768
#define PJ_BLO 49152
#define PJ_STAGE 65536
#define PJ_SMEM (2 * PJ_STAGE)

__global__ void __launch_bounds__(512, 1) proj_mma_kernel(
    const float* __restrict__ keys, const float* __restrict__ values)
{
    const int dt = blockIdx.x;
    const int b  = blockIdx.y;
    const int w  = blockIdx.z;
    const bool kpass = (w == 0);       // K projection keeps the ah*bl pass

    const float* __restrict__ X = (w ? values : keys) + (size_t)b * Nn * Dn + dt * 128;
    const uint32_t* __restrict__ PTh = g_PTh + (size_t)w * Kn * (Nn / 2);
    const uint32_t* __restrict__ PTl = g_PTl + (size_t)w * Kn * (Nn / 2);
    uint32_t* __restrict__ Gh = (w ? g_vph : g_kph) + (size_t)b * Kn * HD + dt * 64;
    uint32_t* __restrict__ Gl = (w ? g_vpl : g_kpl) + (size_t)b * Kn * HD + dt * 64;

    extern __shared__ __align__(1024) unsigned char dsm[];
    const uint32_t sbase = smem_u32(dsm);

    const int tid  = threadIdx.x;
    const int wid  = tid >> 5, lane = tid & 31;
    const int warp_m = (wid >> 2) * 32;
    const int warp_d = (wid & 3) * 32;

    float acc[2][4][4];
    #pragma unroll
    for (int i = 0; i < 2; i++)
        #pragma unroll
        for (int j = 0; j < 4; j++)
            #pragma unroll
            for (int q = 0; q < 4; q++) acc[i][j][q] = 0.0f;

    uint4  pA[4];
    float4 pB[4];

    #pragma unroll
    for (int u = 0; u < 2; u++) {
        int idx = tid + 512 * u;
        int row = idx >> 3, c8 = idx & 7;
        size_t o = (size_t)row * (Nn / 2) + c8 * 4;
        pA[u]     = *(const uint4*)&PTh[o];
        pA[2 + u] = *(const uint4*)&PTl[o];
    }
    #pragma unroll
    for (int u = 0; u < 4; u++) {
        int idx = tid + 512 * u;
        int row = idx >> 5, c4 = idx & 31;
        pB[u] = *(const float4*)&X[(size_t)row * Dn + c4 * 4];
    }

    for (int c = 0; c < 64; ++c) {
        unsigned char* st = dsm + (c & 1) * PJ_STAGE;

        #pragma unroll
        for (int u = 0; u < 2; u++) {
            int idx = tid + 512 * u;
            int row = idx >> 3, c8 = idx & 7;
            uint32_t off = SWZ128((uint32_t)(row * 128 + c8 * 16));
            *(uint4*)(st + PJ_AHI + off) = pA[u];
            *(uint4*)(st + PJ_ALO + off) = pA[2 + u];
        }
        #pragma unroll
        for (int u = 0; u < 4; u++) {
            int idx = tid + 512 * u;
            int row = idx >> 5, c4 = idx & 31;
            uint2 hh, ll;
            split4h(pB[u], 1.0f, hh, ll);
            uint32_t off = SWZ256((uint32_t)(row * 256 + c4 * 8));
            *(uint2*)(st + PJ_BHI + off) = hh;
            *(uint2*)(st + PJ_BLO + off) = ll;
        }
        __syncthreads();

        if (c < 63) {
            int nb = (c + 1) * 64;
            #pragma unroll
            for (int u = 0; u < 2; u++) {
                int idx = tid + 512 * u;
                int row = idx >> 3, c8 = idx & 7;
                size_t o = (size_t)row * (Nn / 2) + (nb >> 1) + c8 * 4;
                pA[u]     = *(const uint4*)&PTh[o];
                pA[2 + u] = *(const uint4*)&PTl[o];
            }
            #pragma unroll
            for (int u = 0; u < 4; u++) {
                int idx = tid + 512 * u;
                int row = idx >> 5, c4 = idx & 31;
                pB[u] = *(const float4*)&X[(size_t)(nb + row) * Dn + c4 * 4];
            }
        }

        const uint32_t sA = sbase + (c & 1) * PJ_STAGE;
        const uint32_t sB = sA + PJ_BHI;
        #pragma unroll
        for (int ks = 0; ks < 4; ks++) {
            uint32_t ah[2][4], al[2][4];
            #pragma unroll
            for (int mi = 0; mi < 2; mi++) {
                uint32_t off = SWZ128((uint32_t)((warp_m + mi * 16 + (lane & 15)) * 128
                                                 + ks * 32 + (lane >> 4) * 16));
                LDSM4(ah[mi], sA + PJ_AHI + off);
                LDSM4(al[mi], sA + PJ_ALO + off);
            }
            #pragma unroll
            for (int g2 = 0; g2 < 2; g2++) {
                uint32_t offb = SWZ256((uint32_t)((ks * 16 + (lane & 15)) * 256
                                                  + warp_d * 2 + g2 * 32 + (lane >> 4) * 16));
                uint32_t bh[4], bl[4];
                LDSM4T(bh, sB + offb);
                if (kpass) LDSM4T(bl, sB + (PJ_BLO - PJ_BHI) + offb);
                #pragma unroll
                for (int mi = 0; mi < 2; mi++) {
                    #pragma unroll
                    for (int jj = 0; jj < 2; jj++) {
                        float* cc = acc[mi][g2 * 2 + jj];
                        MMA_F16(cc, ah[mi], bh[jj * 2], bh[jj * 2 + 1]);
                        MMA_F16(cc, al[mi], bh[jj * 2], bh[jj * 2 + 1]);
                        if (kpass)
                            MMA_F16(cc, ah[mi], bl[jj * 2], bl[jj * 2 + 1]);
                    }
                }
            }
        }
        __syncthreads();
    }

    // ---- epilogue: split accumulators to fp16 limbs, store pairs ----
    #pragma unroll
    for (int mi = 0; mi < 2; mi++) {
        #pragma unroll
        for (int j = 0; j < 4; j++) {
            int row = warp_m + mi * 16 + (lane >> 2);
            int cp  = (warp_d + j * 8) / 2 + (lane & 3);   // u32 pair column
            float a0 = acc[mi][j][0], a1 = acc[mi][j][1];
            float a2 = acc[mi][j][2], a3 = acc[mi][j][3];
            uint32_t h0 = cvt2h(a1, a0);
            uint32_t l0 = cvt2h(a1 - f16hi(h0), a0 - f16lo(h0));
            uint32_t h1 = cvt2h(a3, a2);
            uint32_t l1 = cvt2h(a3 - f16hi(h1), a2 - f16lo(h1));
            Gh[(size_t)row * HD + cp]       = h0;
            Gl[(size_t)row * HD + cp]       = l0;
            Gh[(size_t)(row + 8) * HD + cp] = h1;
            Gl[(size_t)(row + 8) * HD + cp] = l1;
        }
    }
}

// ============================================================================
// Kernel 2: tensor-core attention; 1 tile per CTA; warp-pair decoupling.
//   GEMM1: 2-pass (Q 2-limb x K hi) — K lo limb never loaded.
//   GEMM2: 2-pass (P single fp16 x V 2-limb).
//   P stored split by k-half at 128 B/row into QHI/QLO (pair-private rows).
// ============================================================================
#define AT_QHI  0
#define AT_QLO  16384
#define AT_KHI  32768
#define AT_VHI  65536
#define AT_VLO  81920
#define AT_SMAX 98304
#define AT_SSUM 99328
#define AT_SMEM 100352

__global__ void __launch_bounds__(256, 2) attn_mma_kernel(
    const float* __restrict__ qg, float* __restrict__ outg)
{
    const int nt = blockIdx.x;
    const int h  = blockIdx.y;
    const int b  = blockIdx.z;

    extern __shared__ __align__(1024) unsigned char smb[];
    const uint32_t sbase = smem_u32(smb);
    float* smax = (float*)(smb + AT_SMAX);
    float* ssum = (float*)(smb + AT_SSUM);

    const int tid  = threadIdx.x;
    const int wid  = tid >> 5, lane = tid & 31;
    const int g    = lane >> 2, tk = lane & 3;
    const int wm   = (wid >> 1) * 32;
    const int kh   = wid & 1;
    const int barid = 1 + (wid >> 1);     // named barrier per warp pair

    // ---- K(hi)/V limb fill (direct 16B copies) + Q fill+split, one phase ----
    {
        const size_t kvb = (size_t)b * Kn * HD + h * 32;
        #pragma unroll
        for (int t = 0; t < 4; t++) {
            int idx = tid + 256 * t;
            int row = idx >> 3, u4 = idx & 7;
            size_t o = kvb + (size_t)row * HD + u4 * 4;
            uint32_t off = SWZ128((uint32_t)(row * 128 + u4 * 16));
            *(uint4*)(smb + AT_KHI + off) = *(const uint4*)&g_kph[o];
            *(uint4*)(smb + AT_VHI + off) = *(const uint4*)&g_vph[o];
            *(uint4*)(smb + AT_VLO + off) = *(const uint4*)&g_vpl[o];
        }
        const size_t qbase = ((size_t)b * Nn + (size_t)nt * 128) * Dn + h * 64;
        #pragma unroll
        for (int t = 0; t < 8; t++) {
            int idx = tid + 256 * t;
            int row = idx >> 4, c4 = idx & 15;
            size_t go = (size_t)row * Dn + c4 * 4;
            uint32_t off = SWZ128((uint32_t)(row * 128 + c4 * 8));
            uint2 hh, ll;
            split4h(*(const float4*)&qg[qbase + go], 0.125f, hh, ll);
            *(uint2*)(smb + AT_QHI + off) = hh;
            *(uint2*)(smb + AT_QLO + off) = ll;
        }
    }
    __syncthreads();   // only CTA-wide barrier: striped loads -> per-pair reads

    // ---- GEMM1: dots[128n x 128k]; warp tile 32n x 64k; 2-pass ----
    float acc[2][8][4];
    #pragma unroll
    for (int i = 0; i < 2; i++)
        #pragma unroll
        for (int j = 0; j < 8; j++)
            #pragma unroll
            for (int q = 0; q < 4; q++) acc[i][j][q] = 0.0f;

    {
        const int wk = kh * 64;
        #pragma unroll
        for (int ks = 0; ks < 4; ks++) {
            uint32_t ah[2][4], al[2][4];
            #pragma unroll
            for (int mi = 0; mi < 2; mi++) {
                uint32_t off = SWZ128((uint32_t)((wm + mi * 16 + (lane & 15)) * 128
                                                 + ks * 32 + (lane >> 4) * 16));
                LDSM4(ah[mi], sbase + AT_QHI + off);
                LDSM4(al[mi], sbase + AT_QLO + off);
            }
            #pragma unroll
            for (int jj = 0; jj < 4; jj++) {
                uint32_t offb = SWZ128((uint32_t)((wk + jj * 16 + (lane & 15)) * 128
                                                  + ks * 32 + (lane >> 4) * 16));
                uint32_t bh[4];
                LDSM4(bh, sbase + AT_KHI + offb);
                // non-trans B pairing: tile(2jj)=(r0,r2), tile(2jj+1)=(r1,r3)
                #pragma unroll
                for (int mi = 0; mi < 2; mi++) {
                    float* c0 = acc[mi][jj * 2];
                    MMA_F16(c0, ah[mi], bh[0], bh[2]);
                    MMA_F16(c0, al[mi], bh[0], bh[2]);
                    float* c1v = acc[mi][jj * 2 + 1];
                    MMA_F16(c1v, ah[mi], bh[1], bh[3]);
                    MMA_F16(c1v, al[mi], bh[1], bh[3]);
                }
            }
        }
    }

    // ---- softmax part 1: row max (pair-local) ----
    #pragma unroll
    for (int mi = 0; mi < 2; mi++) {
        #pragma unroll
        for (int h2 = 0; h2 < 2; h2++) {
            float m = acc[mi][0][h2 * 2];
            #pragma unroll
            for (int j = 0; j < 8; j++)
                m = fmaxf(m, fmaxf(acc[mi][j][h2 * 2], acc[mi][j][h2 * 2 + 1]));
            m = fmaxf(m, __shfl_xor_sync(0xffffffffu, m, 1));
            m = fmaxf(m, __shfl_xor_sync(0xffffffffu, m, 2));
            if (tk == 0) smax[(wm + mi * 16 + g + h2 * 8) * 2 + kh] = m;
        }
    }
    BAR_PAIR(barid);

    // ---- softmax part 2: exp, write P (own k-half region, 128 B rows);
    //      accumulate rowsum from the ROUNDED P; store via generic pointer ----
    {
        unsigned char* pptr = smb + (kh ? AT_QLO : AT_QHI);
        #pragma unroll
        for (int mi = 0; mi < 2; mi++) {
            #pragma unroll
            for (int h2 = 0; h2 < 2; h2++) {
                int row = wm + mi * 16 + g + h2 * 8;
                float M = fmaxf(smax[row * 2], smax[row * 2 + 1]);
                float s = 0.0f;
                #pragma unroll
                for (int j = 0; j < 8; j++) {
                    float x0 = __expf(acc[mi][j][h2 * 2]     - M);
                    float x1 = __expf(acc[mi][j][h2 * 2 + 1] - M);
                    uint32_t ph = cvt2h(x1, x0);
                    s += f16lo(ph) + f16hi(ph);
                    uint32_t off = SWZ128((uint32_t)(row * 128 + j * 16 + tk * 4));
                    *(uint32_t*)(pptr + off) = ph;
                }
                s += __shfl_xor_sync(0xffffffffu, s, 1);
                s += __shfl_xor_sync(0xffffffffu, s, 2);
                if (tk == 0) ssum[row * 2 + kh] = s;
            }
        }
    }
    BAR_PAIR(barid);

    // ---- GEMM2: out = P . VV; 2-pass (P single, V 2-limb) ----
    float o[2][4][4];
    #pragma unroll
    for (int i = 0; i < 2; i++)
        #pragma unroll
        for (int j = 0; j < 4; j++)
            #pragma unroll
            for (int q = 0; q < 4; q++) o[i][j][q] = 0.0f;

    {
        const int wdh = kh * 32;
        #pragma unroll
        for (int ks = 0; ks < 8; ks++) {
            const uint32_t pbase = sbase + (ks < 4 ? AT_QHI : AT_QLO);
            uint32_t ah[2][4];
            #pragma unroll
            for (int mi = 0; mi < 2; mi++) {
                uint32_t off = SWZ128((uint32_t)((wm + mi * 16 + (lane & 15)) * 128
                                                 + (ks & 3) * 32 + (lane >> 4) * 16));
                LDSM4(ah[mi], pbase + off);
            }
            #pragma unroll
            for (int g2 = 0; g2 < 2; g2++) {
                uint32_t offb = SWZ128((uint32_t)((ks * 16 + (lane & 15)) * 128
                                                  + wdh * 2 + g2 * 32 + (lane >> 4) * 16));
                uint32_t bh[4], bl[4];
                LDSM4T(bh, sbase + AT_VHI + offb);
                LDSM4T(bl, sbase + AT_VLO + offb);
                // trans B pairing: tile(g2*2)=(r0,r1), tile(g2*2+1)=(r2,r3)
                #pragma unroll
                for (int mi = 0; mi < 2; mi++) {
                    #pragma unroll
                    for (int jj = 0; jj < 2; jj++) {
                        float* cc = o[mi][g2 * 2 + jj];
                        MMA_F16(cc, ah[mi], bh[jj * 2], bh[jj * 2 + 1]);
                        MMA_F16(cc, ah[mi], bl[jj * 2], bl[jj * 2 + 1]);
                    }
                }
            }
        }
    }

    // ---- epilogue: normalize by 1/rowsum, store ----
    {
        const int wdh = kh * 32;
        const size_t obase = ((size_t)b * Nn + (size_t)nt * 128) * Dn + h * 64;
        #pragma unroll
        for (int mi = 0; mi < 2; mi++) {
            int r0 = wm + mi * 16 + g;
            int r1 = r0 + 8;
            float ri0 = 1.0f / (ssum[r0 * 2] + ssum[r0 * 2 + 1]);
            float ri1 = 1.0f / (ssum[r1 * 2] + ssum[r1 * 2 + 1]);
            #pragma unroll
            for (int j = 0; j < 4; j++) {
                int col = wdh + j * 8 + tk * 2;
                *(float2*)&outg[obase + (size_t)r0 * Dn + col] =
                    make_float2(o[mi][j][0] * ri0, o[mi][j][1] * ri0);
                *(float2*)&outg[obase + (size_t)r1 * Dn + col] =
                    make_float2(o[mi][j][2] * ri1, o[mi][j][3] * ri1);
            }
        }
    }
}

// ============================================================================
// Launch
// ============================================================================
extern "C" void kernel_launch(void* const* d_in, const int* in_sizes, int n_in,
                              void* d_out, int out_size)
{
    const float* q      = (const float*)d_in[0];
    const float* keys   = (const float*)d_in[1];
    const float* values = (const float*)d_in[2];
    const float* pk     = (const float*)d_in[3];
    const float* pv     = (const float*)d_in[4];
    float* out = (float*)d_out;

    cudaFuncSetAttribute(proj_mma_kernel,
                         cudaFuncAttributeMaxDynamicSharedMemorySize, PJ_SMEM);
    cudaFuncSetAttribute(attn_mma_kernel,
                         cudaFuncAttributeMaxDynamicSharedMemorySize, AT_SMEM);

    ptrans_kernel<<<dim3(Nn / 32, 2), 256>>>(pk, pv);
    proj_mma_kernel<<<dim3(8, Bsz, 2), 512, PJ_SMEM>>>(keys, values);
    attn_mma_kernel<<<dim3(Nn / 128, Hn, Bsz), 256, AT_SMEM>>>(q, out);
}

// round 14
// speedup vs baseline: 1.4591x; 1.3556x over previous
#include <cuda_runtime.h>
#include <cuda_fp16.h>
#include <cstdint>
#include <cstddef>

// Problem constants
#define Bsz 8
#define Hn  16
#define Nn  4096
#define DHn 64
#define Kn  128
#define Dn  1024
#define HD  (Dn / 2)     // u32 (fp16-pair) row stride

// Device scratch (no allocs allowed)
__device__ uint32_t g_kph[Bsz * Kn * HD];          // projected K hi limb (fp16 pairs)
__device__ uint32_t g_vph[Bsz * Kn * HD];          // projected V hi limb
__device__ uint32_t g_PTh[2 * Kn * (Nn / 2)];      // P^T hi f16 pairs [w][k][n/2]
__device__ uint32_t g_PTl[2 * Kn * (Nn / 2)];      // P^T lo f16 pairs

typedef unsigned long long u64;

// ---------------------------------------------------------------------------
// helpers (fp16 limbs)
// ---------------------------------------------------------------------------
__device__ __forceinline__ uint32_t cvt2h(float hi_elem, float lo_elem) {
    uint32_t r;
    asm("cvt.rn.f16x2.f32 %0, %1, %2;" : "=r"(r) : "f"(hi_elem), "f"(lo_elem));
    return r;
}
__device__ __forceinline__ float f16lo(uint32_t p) {
    return __half2float(__ushort_as_half((unsigned short)(p & 0xffffu)));
}
__device__ __forceinline__ float f16hi(uint32_t p) {
    return __half2float(__ushort_as_half((unsigned short)(p >> 16)));
}

#define SWZ128(x) ((x) ^ (((x) >> 3) & 0x70))
#define SWZ256(x) ((x) ^ (((x) >> 4) & 0x70))

#define LDSM4(r, a) \
    asm volatile("ldmatrix.sync.aligned.m8n8.x4.shared.b16 {%0,%1,%2,%3}, [%4];" \
        : "=r"((r)[0]), "=r"((r)[1]), "=r"((r)[2]), "=r"((r)[3]) : "r"(a))
#define LDSM4T(r, a) \
    asm volatile("ldmatrix.sync.aligned.m8n8.x4.trans.shared.b16 {%0,%1,%2,%3}, [%4];" \
        : "=r"((r)[0]), "=r"((r)[1]), "=r"((r)[2]), "=r"((r)[3]) : "r"(a))
#define MMA_F16(c, a, b0v, b1v) \
    asm volatile("mma.sync.aligned.m16n8k16.row.col.f32.f16.f16.f32 " \
        "{%0,%1,%2,%3}, {%4,%5,%6,%7}, {%8,%9}, {%0,%1,%2,%3};" \
        : "+f"((c)[0]), "+f"((c)[1]), "+f"((c)[2]), "+f"((c)[3]) \
        : "r"((a)[0]), "r"((a)[1]), "r"((a)[2]), "r"((a)[3]), "r"(b0v), "r"(b1v))

// 64-thread named barrier for a warp pair (ids 1..4)
#define BAR_PAIR(id) asm volatile("bar.sync %0, 64;" :: "r"(id) : "memory")

__device__ __forceinline__ uint32_t smem_u32(const void* p) {
    uint32_t a;
    asm("{ .reg .u64 t; cvta.to.shared.u64 t, %1; cvt.u32.u64 %0, t; }" : "=r"(a) : "l"(p));
    return a;
}

// split a float4 (optionally scaled) into hi/lo f16x2 pairs
__device__ __forceinline__ void split4h(float4 v, float s, uint2& h, uint2& l) {
    v.x *= s; v.y *= s; v.z *= s; v.w *= s;
    uint32_t h01 = cvt2h(v.y, v.x);
    uint32_t h23 = cvt2h(v.w, v.z);
    float h0 = f16lo(h01), h1 = f16hi(h01);
    float h2 = f16lo(h23), h3 = f16hi(h23);
    uint32_t l01 = cvt2h(v.y - h1, v.x - h0);
    uint32_t l23 = cvt2h(v.w - h3, v.z - h2);
    h = make_uint2(h01, h23);
    l = make_uint2(l01, l23);
}

// ============================================================================
// Kernel 0: transpose P [4096 n][128 k] -> split-f16 PT [w][128 k][4096 n]
// ============================================================================
__global__ void __launch_bounds__(256) ptrans_kernel(
    const float* __restrict__ pk, const float* __restrict__ pv)
{
    __shared__ float sT[128][33];
    const int t  = threadIdx.x;
    const int n0 = blockIdx.x * 32;
    const int w  = blockIdx.y;
    const float* __restrict__ P = w ? pv : pk;

    #pragma unroll
    for (int i = 0; i < 16; i++) {
        int idx = t + 256 * i;
        int r = idx >> 7, c = idx & 127;
        sT[c][r] = P[(size_t)(n0 + r) * Kn + c];
    }
    __syncthreads();

    uint32_t* __restrict__ oh = g_PTh + (size_t)w * Kn * (Nn / 2);
    uint32_t* __restrict__ ol = g_PTl + (size_t)w * Kn * (Nn / 2);
    #pragma unroll
    for (int i = 0; i < 8; i++) {
        int idx = t + 256 * i;
        int k = idx >> 4, pr = idx & 15;
        float x0 = sT[k][2 * pr], x1 = sT[k][2 * pr + 1];
        uint32_t h = cvt2h(x1, x0);
        float h0 = f16lo(h), h1 = f16hi(h);
        uint32_t l = cvt2h(x1 - h1, x0 - h0);
        size_t o = (size_t)k * (Nn / 2) + (n0 >> 1) + pr;
        oh[o] = h;
        ol[o] = l;
    }
}

// ============================================================================
// Kernel 1: mma.sync f16-split projection, uniform 2-pass:
//   C = (PT hi + PT lo) x X_hi   (X lo never staged)
//   Epilogue emits hi limb only (attn consumes fp16 K/V).
// ============================================================================
#define PJ_AHI 0
#define PJ_ALO 16384
#define PJ_BHI 32768
#define PJ_STAGE 49152
#define PJ_SMEM (2 * PJ_STAGE)

__global__ void __launch_bounds__(512, 1) proj_mma_kernel(
    const float* __restrict__ keys, const float* __restrict__ values)
{
    const int dt = blockIdx.x;
    const int b  = blockIdx.y;
    const int w  = blockIdx.z;

    const float* __restrict__ X = (w ? values : keys) + (size_t)b * Nn * Dn + dt * 128;
    const uint32_t* __restrict__ PTh = g_PTh + (size_t)w * Kn * (Nn / 2);
    const uint32_t* __restrict__ PTl = g_PTl + (size_t)w * Kn * (Nn / 2);
    uint32_t* __restrict__ Gh = (w ? g_vph : g_kph) + (size_t)b * Kn * HD + dt * 64;

    extern __shared__ __align__(1024) unsigned char dsm[];
    const uint32_t sbase = smem_u32(dsm);

    const int tid  = threadIdx.x;
    const int wid  = tid >> 5, lane = tid & 31;
    const int warp_m = (wid >> 2) * 32;
    const int warp_d = (wid & 3) * 32;

    float acc[2][4][4];
    #pragma unroll
    for (int i = 0; i < 2; i++)
        #pragma unroll
        for (int j = 0; j < 4; j++)
            #pragma unroll
            for (int q = 0; q < 4; q++) acc[i][j][q] = 0.0f;

    uint4  pA[4];
    float4 pB[4];

    #pragma unroll
    for (int u = 0; u < 2; u++) {
        int idx = tid + 512 * u;
        int row = idx >> 3, c8 = idx & 7;
        size_t o = (size_t)row * (Nn / 2) + c8 * 4;
        pA[u]     = *(const uint4*)&PTh[o];
        pA[2 + u] = *(const uint4*)&PTl[o];
    }
    #pragma unroll
    for (int u = 0; u < 4; u++) {
        int idx = tid + 512 * u;
        int row = idx >> 5, c4 = idx & 31;
        pB[u] = *(const float4*)&X[(size_t)row * Dn + c4 * 4];
    }

    for (int c = 0; c < 64; ++c) {
        unsigned char* st = dsm + (c & 1) * PJ_STAGE;

        #pragma unroll
        for (int u = 0; u < 2; u++) {
            int idx = tid + 512 * u;
            int row = idx >> 3, c8 = idx & 7;
            uint32_t off = SWZ128((uint32_t)(row * 128 + c8 * 16));
            *(uint4*)(st + PJ_AHI + off) = pA[u];
            *(uint4*)(st + PJ_ALO + off) = pA[2 + u];
        }
        #pragma unroll
        for (int u = 0; u < 4; u++) {
            int idx = tid + 512 * u;
            int row = idx >> 5, c4 = idx & 31;
            float4 v = pB[u];
            uint2 hh;
            hh.x = cvt2h(v.y, v.x);
            hh.y = cvt2h(v.w, v.z);
            uint32_t off = SWZ256((uint32_t)(row * 256 + c4 * 8));
            *(uint2*)(st + PJ_BHI + off) = hh;
        }
        __syncthreads();

        if (c < 63) {
            int nb = (c + 1) * 64;
            #pragma unroll
            for (int u = 0; u < 2; u++) {
                int idx = tid + 512 * u;
                int row = idx >> 3, c8 = idx & 7;
                size_t o = (size_t)row * (Nn / 2) + (nb >> 1) + c8 * 4;
                pA[u]     = *(const uint4*)&PTh[o];
                pA[2 + u] = *(const uint4*)&PTl[o];
            }
            #pragma unroll
            for (int u = 0; u < 4; u++) {
                int idx = tid + 512 * u;
                int row = idx >> 5, c4 = idx & 31;
                pB[u] = *(const float4*)&X[(size_t)(nb + row) * Dn + c4 * 4];
            }
        }

        const uint32_t sA = sbase + (c & 1) * PJ_STAGE;
        const uint32_t sB = sA + PJ_BHI;
        #pragma unroll
        for (int ks = 0; ks < 4; ks++) {
            uint32_t ah[2][4], al[2][4];
            #pragma unroll
            for (int mi = 0; mi < 2; mi++) {
                uint32_t off = SWZ128((uint32_t)((warp_m + mi * 16 + (lane & 15)) * 128
                                                 + ks * 32 + (lane >> 4) * 16));
                LDSM4(ah[mi], sA + PJ_AHI + off);
                LDSM4(al[mi], sA + PJ_ALO + off);
            }
            #pragma unroll
            for (int g2 = 0; g2 < 2; g2++) {
                uint32_t offb = SWZ256((uint32_t)((ks * 16 + (lane & 15)) * 256
                                                  + warp_d * 2 + g2 * 32 + (lane >> 4) * 16));
                uint32_t bh[4];
                LDSM4T(bh, sB + offb);
                #pragma unroll
                for (int mi = 0; mi < 2; mi++) {
                    #pragma unroll
                    for (int jj = 0; jj < 2; jj++) {
                        float* cc = acc[mi][g2 * 2 + jj];
                        MMA_F16(cc, ah[mi], bh[jj * 2], bh[jj * 2 + 1]);
                        MMA_F16(cc, al[mi], bh[jj * 2], bh[jj * 2 + 1]);
                    }
                }
            }
        }
        __syncthreads();
    }

    // ---- epilogue: hi limb only ----
    #pragma unroll
    for (int mi = 0; mi < 2; mi++) {
        #pragma unroll
        for (int j = 0; j < 4; j++) {
            int row = warp_m + mi * 16 + (lane >> 2);
            int cp  = (warp_d + j * 8) / 2 + (lane & 3);   // u32 pair column
            uint32_t h0 = cvt2h(acc[mi][j][1], acc[mi][j][0]);
            uint32_t h1 = cvt2h(acc[mi][j][3], acc[mi][j][2]);
            Gh[(size_t)row * HD + cp]       = h0;
            Gh[(size_t)(row + 8) * HD + cp] = h1;
        }
    }
}

// ============================================================================
// Kernel 2: tensor-core attention; 1 tile per CTA; warp-pair decoupling.
//   GEMM1: 2-pass (Q 2-limb x K hi).
//   GEMM2: 1-pass (P single fp16 x V hi).
//   P stored split by k-half at 128 B/row into QHI/QLO (pair-private rows).
// ============================================================================
#define AT_QHI  0
#define AT_QLO  16384
#define AT_KHI  32768
#define AT_VHI  49152
#define AT_SMAX 65536
#define AT_SSUM 66560
#define AT_SMEM 67584

__global__ void __launch_bounds__(256, 2) attn_mma_kernel(
    const float* __restrict__ qg, float* __restrict__ outg)
{
    const int nt = blockIdx.x;
    const int h  = blockIdx.y;
    const int b  = blockIdx.z;

    extern __shared__ __align__(1024) unsigned char smb[];
    const uint32_t sbase = smem_u32(smb);
    float* smax = (float*)(smb + AT_SMAX);
    float* ssum = (float*)(smb + AT_SSUM);

    const int tid  = threadIdx.x;
    const int wid  = tid >> 5, lane = tid & 31;
    const int g    = lane >> 2, tk = lane & 3;
    const int wm   = (wid >> 1) * 32;
    const int kh   = wid & 1;
    const int barid = 1 + (wid >> 1);     // named barrier per warp pair

    // ---- K(hi)/V(hi) fill (direct 16B copies) + Q fill+split, one phase ----
    {
        const size_t kvb = (size_t)b * Kn * HD + h * 32;
        #pragma unroll
        for (int t = 0; t < 4; t++) {
            int idx = tid + 256 * t;
            int row = idx >> 3, u4 = idx & 7;
            size_t o = kvb + (size_t)row * HD + u4 * 4;
            uint32_t off = SWZ128((uint32_t)(row * 128 + u4 * 16));
            *(uint4*)(smb + AT_KHI + off) = *(const uint4*)&g_kph[o];
            *(uint4*)(smb + AT_VHI + off) = *(const uint4*)&g_vph[o];
        }
        const size_t qbase = ((size_t)b * Nn + (size_t)nt * 128) * Dn + h * 64;
        #pragma unroll
        for (int t = 0; t < 8; t++) {
            int idx = tid + 256 * t;
            int row = idx >> 4, c4 = idx & 15;
            size_t go = (size_t)row * Dn + c4 * 4;
            uint32_t off = SWZ128((uint32_t)(row * 128 + c4 * 8));
            uint2 hh, ll;
            split4h(*(const float4*)&qg[qbase + go], 0.125f, hh, ll);
            *(uint2*)(smb + AT_QHI + off) = hh;
            *(uint2*)(smb + AT_QLO + off) = ll;
        }
    }
    __syncthreads();   // only CTA-wide barrier: striped loads -> per-pair reads

    // ---- GEMM1: dots[128n x 128k]; warp tile 32n x 64k; 2-pass ----
    float acc[2][8][4];
    #pragma unroll
    for (int i = 0; i < 2; i++)
        #pragma unroll
        for (int j = 0; j < 8; j++)
            #pragma unroll
            for (int q = 0; q < 4; q++) acc[i][j][q] = 0.0f;

    {
        const int wk = kh * 64;
        #pragma unroll
        for (int ks = 0; ks < 4; ks++) {
            uint32_t ah[2][4], al[2][4];
            #pragma unroll
            for (int mi = 0; mi < 2; mi++) {
                uint32_t off = SWZ128((uint32_t)((wm + mi * 16 + (lane & 15)) * 128
                                                 + ks * 32 + (lane >> 4) * 16));
                LDSM4(ah[mi], sbase + AT_QHI + off);
                LDSM4(al[mi], sbase + AT_QLO + off);
            }
            #pragma unroll
            for (int jj = 0; jj < 4; jj++) {
                uint32_t offb = SWZ128((uint32_t)((wk + jj * 16 + (lane & 15)) * 128
                                                  + ks * 32 + (lane >> 4) * 16));
                uint32_t bh[4];
                LDSM4(bh, sbase + AT_KHI + offb);
                // non-trans B pairing: tile(2jj)=(r0,r2), tile(2jj+1)=(r1,r3)
                #pragma unroll
                for (int mi = 0; mi < 2; mi++) {
                    float* c0 = acc[mi][jj * 2];
                    MMA_F16(c0, ah[mi], bh[0], bh[2]);
                    MMA_F16(c0, al[mi], bh[0], bh[2]);
                    float* c1v = acc[mi][jj * 2 + 1];
                    MMA_F16(c1v, ah[mi], bh[1], bh[3]);
                    MMA_F16(c1v, al[mi], bh[1], bh[3]);
                }
            }
        }
    }

    // ---- softmax part 1: row max (pair-local) ----
    #pragma unroll
    for (int mi = 0; mi < 2; mi++) {
        #pragma unroll
        for (int h2 = 0; h2 < 2; h2++) {
            float m = acc[mi][0][h2 * 2];
            #pragma unroll
            for (int j = 0; j < 8; j++)
                m = fmaxf(m, fmaxf(acc[mi][j][h2 * 2], acc[mi][j][h2 * 2 + 1]));
            m = fmaxf(m, __shfl_xor_sync(0xffffffffu, m, 1));
            m = fmaxf(m, __shfl_xor_sync(0xffffffffu, m, 2));
            if (tk == 0) smax[(wm + mi * 16 + g + h2 * 8) * 2 + kh] = m;
        }
    }
    BAR_PAIR(barid);

    // ---- softmax part 2: exp, write P (own k-half region, 128 B rows);
    //      accumulate rowsum from the ROUNDED P; store via generic pointer ----
    {
        unsigned char* pptr = smb + (kh ? AT_QLO : AT_QHI);
        #pragma unroll
        for (int mi = 0; mi < 2; mi++) {
            #pragma unroll
            for (int h2 = 0; h2 < 2; h2++) {
                int row = wm + mi * 16 + g + h2 * 8;
                float M = fmaxf(smax[row * 2], smax[row * 2 + 1]);
                float s = 0.0f;
                #pragma unroll
                for (int j = 0; j < 8; j++) {
                    float x0 = __expf(acc[mi][j][h2 * 2]     - M);
                    float x1 = __expf(acc[mi][j][h2 * 2 + 1] - M);
                    uint32_t ph = cvt2h(x1, x0);
                    s += f16lo(ph) + f16hi(ph);
                    uint32_t off = SWZ128((uint32_t)(row * 128 + j * 16 + tk * 4));
                    *(uint32_t*)(pptr + off) = ph;
                }
                s += __shfl_xor_sync(0xffffffffu, s, 1);
                s += __shfl_xor_sync(0xffffffffu, s, 2);
                if (tk == 0) ssum[row * 2 + kh] = s;
            }
        }
    }
    BAR_PAIR(barid);

    // ---- GEMM2: out = P . VV; 1-pass (P single, V hi) ----
    float o[2][4][4];
    #pragma unroll
    for (int i = 0; i < 2; i++)
        #pragma unroll
        for (int j = 0; j < 4; j++)
            #pragma unroll
            for (int q = 0; q < 4; q++) o[i][j][q] = 0.0f;

    {
        const int wdh = kh * 32;
        #pragma unroll
        for (int ks = 0; ks < 8; ks++) {
            const uint32_t pbase = sbase + (ks < 4 ? AT_QHI : AT_QLO);
            uint32_t ah[2][4];
            #pragma unroll
            for (int mi = 0; mi < 2; mi++) {
                uint32_t off = SWZ128((uint32_t)((wm + mi * 16 + (lane & 15)) * 128
                                                 + (ks & 3) * 32 + (lane >> 4) * 16));
                LDSM4(ah[mi], pbase + off);
            }
            #pragma unroll
            for (int g2 = 0; g2 < 2; g2++) {
                uint32_t offb = SWZ128((uint32_t)((ks * 16 + (lane & 15)) * 128
                                                  + wdh * 2 + g2 * 32 + (lane >> 4) * 16));
                uint32_t bh[4];
                LDSM4T(bh, sbase + AT_VHI + offb);
                // trans B pairing: tile(g2*2)=(r0,r1), tile(g2*2+1)=(r2,r3)
                #pragma unroll
                for (int mi = 0; mi < 2; mi++) {
                    #pragma unroll
                    for (int jj = 0; jj < 2; jj++) {
                        float* cc = o[mi][g2 * 2 + jj];
                        MMA_F16(cc, ah[mi], bh[jj * 2], bh[jj * 2 + 1]);
                    }
                }
            }
        }
    }

    // ---- epilogue: normalize by 1/rowsum, store ----
    {
        const int wdh = kh * 32;
        const size_t obase = ((size_t)b * Nn + (size_t)nt * 128) * Dn + h * 64;
        #pragma unroll
        for (int mi = 0; mi < 2; mi++) {
            int r0 = wm + mi * 16 + g;
            int r1 = r0 + 8;
            float ri0 = 1.0f / (ssum[r0 * 2] + ssum[r0 * 2 + 1]);
            float ri1 = 1.0f / (ssum[r1 * 2] + ssum[r1 * 2 + 1]);
            #pragma unroll
            for (int j = 0; j < 4; j++) {
                int col = wdh + j * 8 + tk * 2;
                *(float2*)&outg[obase + (size_t)r0 * Dn + col] =
                    make_float2(o[mi][j][0] * ri0, o[mi][j][1] * ri0);
                *(float2*)&outg[obase + (size_t)r1 * Dn + col] =
                    make_float2(o[mi][j][2] * ri1, o[mi][j][3] * ri1);
            }
        }
    }
}

// ============================================================================
// Launch
// ============================================================================
extern "C" void kernel_launch(void* const* d_in, const int* in_sizes, int n_in,
                              void* d_out, int out_size)
{
    const float* q      = (const float*)d_in[0];
    const float* keys   = (const float*)d_in[1];
    const float* values = (const float*)d_in[2];
    const float* pk     = (const float*)d_in[3];
    const float* pv     = (const float*)d_in[4];
    float* out = (float*)d_out;

    cudaFuncSetAttribute(proj_mma_kernel,
                         cudaFuncAttributeMaxDynamicSharedMemorySize, PJ_SMEM);
    cudaFuncSetAttribute(attn_mma_kernel,
                         cudaFuncAttributeMaxDynamicSharedMemorySize, AT_SMEM);

    ptrans_kernel<<<dim3(Nn / 32, 2), 256>>>(pk, pv);
    proj_mma_kernel<<<dim3(8, Bsz, 2), 512, PJ_SMEM>>>(keys, values);
    attn_mma_kernel<<<dim3(Nn / 128, Hn, Bsz), 256, AT_SMEM>>>(q, out);
}

// round 15
// speedup vs baseline: 1.6962x; 1.1625x over previous
#include <cuda_runtime.h>
#include <cuda_fp16.h>
#include <cstdint>
#include <cstddef>

// Problem constants
#define Bsz 8
#define Hn  16
#define Nn  4096
#define DHn 64
#define Kn  128
#define Dn  1024
#define HD  (Dn / 2)     // u32 (fp16-pair) row stride

// Device scratch (no allocs allowed)
__device__ uint32_t g_kph[Bsz * Kn * HD];          // projected K hi limb (fp16 pairs)
__device__ uint32_t g_vph[Bsz * Kn * HD];          // projected V hi limb
__device__ uint32_t g_PTh[2 * Kn * (Nn / 2)];      // P^T f16 pairs [w][k][n/2]

typedef unsigned long long u64;

// ---------------------------------------------------------------------------
// helpers (fp16)
// ---------------------------------------------------------------------------
__device__ __forceinline__ uint32_t cvt2h(float hi_elem, float lo_elem) {
    uint32_t r;
    asm("cvt.rn.f16x2.f32 %0, %1, %2;" : "=r"(r) : "f"(hi_elem), "f"(lo_elem));
    return r;
}
__device__ __forceinline__ float f16lo(uint32_t p) {
    return __half2float(__ushort_as_half((unsigned short)(p & 0xffffu)));
}
__device__ __forceinline__ float f16hi(uint32_t p) {
    return __half2float(__ushort_as_half((unsigned short)(p >> 16)));
}

#define SWZ128(x) ((x) ^ (((x) >> 3) & 0x70))
#define SWZ256(x) ((x) ^ (((x) >> 4) & 0x70))

#define LDSM4(r, a) \
    asm volatile("ldmatrix.sync.aligned.m8n8.x4.shared.b16 {%0,%1,%2,%3}, [%4];" \
        : "=r"((r)[0]), "=r"((r)[1]), "=r"((r)[2]), "=r"((r)[3]) : "r"(a))
#define LDSM4T(r, a) \
    asm volatile("ldmatrix.sync.aligned.m8n8.x4.trans.shared.b16 {%0,%1,%2,%3}, [%4];" \
        : "=r"((r)[0]), "=r"((r)[1]), "=r"((r)[2]), "=r"((r)[3]) : "r"(a))
#define MMA_F16(c, a, b0v, b1v) \
    asm volatile("mma.sync.aligned.m16n8k16.row.col.f32.f16.f16.f32 " \
        "{%0,%1,%2,%3}, {%4,%5,%6,%7}, {%8,%9}, {%0,%1,%2,%3};" \
        : "+f"((c)[0]), "+f"((c)[1]), "+f"((c)[2]), "+f"((c)[3]) \
        : "r"((a)[0]), "r"((a)[1]), "r"((a)[2]), "r"((a)[3]), "r"(b0v), "r"(b1v))

// 64-thread named barrier for a warp pair (ids 1..4)
#define BAR_PAIR(id) asm volatile("bar.sync %0, 64;" :: "r"(id) : "memory")

__device__ __forceinline__ uint32_t smem_u32(const void* p) {
    uint32_t a;
    asm("{ .reg .u64 t; cvta.to.shared.u64 t, %1; cvt.u32.u64 %0, t; }" : "=r"(a) : "l"(p));
    return a;
}

// split a float4 (optionally scaled) into hi/lo f16x2 pairs (Q only now)
__device__ __forceinline__ void split4h(float4 v, float s, uint2& h, uint2& l) {
    v.x *= s; v.y *= s; v.z *= s; v.w *= s;
    uint32_t h01 = cvt2h(v.y, v.x);
    uint32_t h23 = cvt2h(v.w, v.z);
    float h0 = f16lo(h01), h1 = f16hi(h01);
    float h2 = f16lo(h23), h3 = f16hi(h23);
    uint32_t l01 = cvt2h(v.y - h1, v.x - h0);
    uint32_t l23 = cvt2h(v.w - h3, v.z - h2);
    h = make_uint2(h01, h23);
    l = make_uint2(l01, l23);
}

// ============================================================================
// Kernel 0: transpose P [4096 n][128 k] -> f16 PT [w][128 k][4096 n] (hi only)
// ============================================================================
__global__ void __launch_bounds__(256) ptrans_kernel(
    const float* __restrict__ pk, const float* __restrict__ pv)
{
    __shared__ float sT[128][33];
    const int t  = threadIdx.x;
    const int n0 = blockIdx.x * 32;
    const int w  = blockIdx.y;
    const float* __restrict__ P = w ? pv : pk;

    #pragma unroll
    for (int i = 0; i < 16; i++) {
        int idx = t + 256 * i;
        int r = idx >> 7, c = idx & 127;
        sT[c][r] = P[(size_t)(n0 + r) * Kn + c];
    }
    __syncthreads();

    uint32_t* __restrict__ oh = g_PTh + (size_t)w * Kn * (Nn / 2);
    #pragma unroll
    for (int i = 0; i < 8; i++) {
        int idx = t + 256 * i;
        int k = idx >> 4, pr = idx & 15;
        float x0 = sT[k][2 * pr], x1 = sT[k][2 * pr + 1];
        oh[(size_t)k * (Nn / 2) + (n0 >> 1) + pr] = cvt2h(x1, x0);
    }
}

// ============================================================================
// Kernel 1: mma.sync fp16 projection, uniform 1-pass:  C = PT_hi x X_hi
//   Epilogue emits fp16 (attn consumes fp16 K/V).
// ============================================================================
#define PJ_AHI 0
#define PJ_BHI 16384
#define PJ_STAGE 32768
#define PJ_SMEM (2 * PJ_STAGE)

__global__ void __launch_bounds__(512, 1) proj_mma_kernel(
    const float* __restrict__ keys, const float* __restrict__ values)
{
    const int dt = blockIdx.x;
    const int b  = blockIdx.y;
    const int w  = blockIdx.z;

    const float* __restrict__ X = (w ? values : keys) + (size_t)b * Nn * Dn + dt * 128;
    const uint32_t* __restrict__ PTh = g_PTh + (size_t)w * Kn * (Nn / 2);
    uint32_t* __restrict__ Gh = (w ? g_vph : g_kph) + (size_t)b * Kn * HD + dt * 64;

    extern __shared__ __align__(1024) unsigned char dsm[];
    const uint32_t sbase = smem_u32(dsm);

    const int tid  = threadIdx.x;
    const int wid  = tid >> 5, lane = tid & 31;
    const int warp_m = (wid >> 2) * 32;
    const int warp_d = (wid & 3) * 32;

    float acc[2][4][4];
    #pragma unroll
    for (int i = 0; i < 2; i++)
        #pragma unroll
        for (int j = 0; j < 4; j++)
            #pragma unroll
            for (int q = 0; q < 4; q++) acc[i][j][q] = 0.0f;

    uint4  pA[2];
    float4 pB[4];

    #pragma unroll
    for (int u = 0; u < 2; u++) {
        int idx = tid + 512 * u;
        int row = idx >> 3, c8 = idx & 7;
        pA[u] = *(const uint4*)&PTh[(size_t)row * (Nn / 2) + c8 * 4];
    }
    #pragma unroll
    for (int u = 0; u < 4; u++) {
        int idx = tid + 512 * u;
        int row = idx >> 5, c4 = idx & 31;
        pB[u] = *(const float4*)&X[(size_t)row * Dn + c4 * 4];
    }

    for (int c = 0; c < 64; ++c) {
        unsigned char* st = dsm + (c & 1) * PJ_STAGE;

        #pragma unroll
        for (int u = 0; u < 2; u++) {
            int idx = tid + 512 * u;
            int row = idx >> 3, c8 = idx & 7;
            uint32_t off = SWZ128((uint32_t)(row * 128 + c8 * 16));
            *(uint4*)(st + PJ_AHI + off) = pA[u];
        }
        #pragma unroll
        for (int u = 0; u < 4; u++) {
            int idx = tid + 512 * u;
            int row = idx >> 5, c4 = idx & 31;
            float4 v = pB[u];
            uint2 hh;
            hh.x = cvt2h(v.y, v.x);
            hh.y = cvt2h(v.w, v.z);
            uint32_t off = SWZ256((uint32_t)(row * 256 + c4 * 8));
            *(uint2*)(st + PJ_BHI + off) = hh;
        }
        __syncthreads();

        if (c < 63) {
            int nb = (c + 1) * 64;
            #pragma unroll
            for (int u = 0; u < 2; u++) {
                int idx = tid + 512 * u;
                int row = idx >> 3, c8 = idx & 7;
                pA[u] = *(const uint4*)&PTh[(size_t)row * (Nn / 2) + (nb >> 1) + c8 * 4];
            }
            #pragma unroll
            for (int u = 0; u < 4; u++) {
                int idx = tid + 512 * u;
                int row = idx >> 5, c4 = idx & 31;
                pB[u] = *(const float4*)&X[(size_t)(nb + row) * Dn + c4 * 4];
            }
        }

        const uint32_t sA = sbase + (c & 1) * PJ_STAGE;
        const uint32_t sB = sA + PJ_BHI;
        #pragma unroll
        for (int ks = 0; ks < 4; ks++) {
            uint32_t ah[2][4];
            #pragma unroll
            for (int mi = 0; mi < 2; mi++) {
                uint32_t off = SWZ128((uint32_t)((warp_m + mi * 16 + (lane & 15)) * 128
                                                 + ks * 32 + (lane >> 4) * 16));
                LDSM4(ah[mi], sA + PJ_AHI + off);
            }
            #pragma unroll
            for (int g2 = 0; g2 < 2; g2++) {
                uint32_t offb = SWZ256((uint32_t)((ks * 16 + (lane & 15)) * 256
                                                  + warp_d * 2 + g2 * 32 + (lane >> 4) * 16));
                uint32_t bh[4];
                LDSM4T(bh, sB + offb);
                #pragma unroll
                for (int mi = 0; mi < 2; mi++) {
                    #pragma unroll
                    for (int jj = 0; jj < 2; jj++) {
                        float* cc = acc[mi][g2 * 2 + jj];
                        MMA_F16(cc, ah[mi], bh[jj * 2], bh[jj * 2 + 1]);
                    }
                }
            }
        }
        __syncthreads();
    }

    // ---- epilogue: fp16 hi only ----
    #pragma unroll
    for (int mi = 0; mi < 2; mi++) {
        #pragma unroll
        for (int j = 0; j < 4; j++) {
            int row = warp_m + mi * 16 + (lane >> 2);
            int cp  = (warp_d + j * 8) / 2 + (lane & 3);   // u32 pair column
            uint32_t h0 = cvt2h(acc[mi][j][1], acc[mi][j][0]);
            uint32_t h1 = cvt2h(acc[mi][j][3], acc[mi][j][2]);
            Gh[(size_t)row * HD + cp]       = h0;
            Gh[(size_t)(row + 8) * HD + cp] = h1;
        }
    }
}

// ============================================================================
// Kernel 2: tensor-core attention; 1 tile per CTA; warp-pair decoupling.
//   GEMM1: 2-pass (Q 2-limb x K hi).
//   GEMM2: 1-pass (P single fp16 x V hi).
//   P stored split by k-half at 128 B/row into QHI/QLO (pair-private rows).
// ============================================================================
#define AT_QHI  0
#define AT_QLO  16384
#define AT_KHI  32768
#define AT_VHI  49152
#define AT_SMAX 65536
#define AT_SSUM 66560
#define AT_SMEM 67584

__global__ void __launch_bounds__(256, 2) attn_mma_kernel(
    const float* __restrict__ qg, float* __restrict__ outg)
{
    const int nt = blockIdx.x;
    const int h  = blockIdx.y;
    const int b  = blockIdx.z;

    extern __shared__ __align__(1024) unsigned char smb[];
    const uint32_t sbase = smem_u32(smb);
    float* smax = (float*)(smb + AT_SMAX);
    float* ssum = (float*)(smb + AT_SSUM);

    const int tid  = threadIdx.x;
    const int wid  = tid >> 5, lane = tid & 31;
    const int g    = lane >> 2, tk = lane & 3;
    const int wm   = (wid >> 1) * 32;
    const int kh   = wid & 1;
    const int barid = 1 + (wid >> 1);     // named barrier per warp pair

    // ---- K(hi)/V(hi) fill (direct 16B copies) + Q fill+split, one phase ----
    {
        const size_t kvb = (size_t)b * Kn * HD + h * 32;
        #pragma unroll
        for (int t = 0; t < 4; t++) {
            int idx = tid + 256 * t;
            int row = idx >> 3, u4 = idx & 7;
            size_t o = kvb + (size_t)row * HD + u4 * 4;
            uint32_t off = SWZ128((uint32_t)(row * 128 + u4 * 16));
            *(uint4*)(smb + AT_KHI + off) = *(const uint4*)&g_kph[o];
            *(uint4*)(smb + AT_VHI + off) = *(const uint4*)&g_vph[o];
        }
        const size_t qbase = ((size_t)b * Nn + (size_t)nt * 128) * Dn + h * 64;
        #pragma unroll
        for (int t = 0; t < 8; t++) {
            int idx = tid + 256 * t;
            int row = idx >> 4, c4 = idx & 15;
            size_t go = (size_t)row * Dn + c4 * 4;
            uint32_t off = SWZ128((uint32_t)(row * 128 + c4 * 8));
            uint2 hh, ll;
            split4h(*(const float4*)&qg[qbase + go], 0.125f, hh, ll);
            *(uint2*)(smb + AT_QHI + off) = hh;
            *(uint2*)(smb + AT_QLO + off) = ll;
        }
    }
    __syncthreads();   // only CTA-wide barrier: striped loads -> per-pair reads

    // ---- GEMM1: dots[128n x 128k]; warp tile 32n x 64k; 2-pass ----
    float acc[2][8][4];
    #pragma unroll
    for (int i = 0; i < 2; i++)
        #pragma unroll
        for (int j = 0; j < 8; j++)
            #pragma unroll
            for (int q = 0; q < 4; q++) acc[i][j][q] = 0.0f;

    {
        const int wk = kh * 64;
        #pragma unroll
        for (int ks = 0; ks < 4; ks++) {
            uint32_t ah[2][4], al[2][4];
            #pragma unroll
            for (int mi = 0; mi < 2; mi++) {
                uint32_t off = SWZ128((uint32_t)((wm + mi * 16 + (lane & 15)) * 128
                                                 + ks * 32 + (lane >> 4) * 16));
                LDSM4(ah[mi], sbase + AT_QHI + off);
                LDSM4(al[mi], sbase + AT_QLO + off);
            }
            #pragma unroll
            for (int jj = 0; jj < 4; jj++) {
                uint32_t offb = SWZ128((uint32_t)((wk + jj * 16 + (lane & 15)) * 128
                                                  + ks * 32 + (lane >> 4) * 16));
                uint32_t bh[4];
                LDSM4(bh, sbase + AT_KHI + offb);
                // non-trans B pairing: tile(2jj)=(r0,r2), tile(2jj+1)=(r1,r3)
                #pragma unroll
                for (int mi = 0; mi < 2; mi++) {
                    float* c0 = acc[mi][jj * 2];
                    MMA_F16(c0, ah[mi], bh[0], bh[2]);
                    MMA_F16(c0, al[mi], bh[0], bh[2]);
                    float* c1v = acc[mi][jj * 2 + 1];
                    MMA_F16(c1v, ah[mi], bh[1], bh[3]);
                    MMA_F16(c1v, al[mi], bh[1], bh[3]);
                }
            }
        }
    }

    // ---- softmax part 1: row max (pair-local) ----
    #pragma unroll
    for (int mi = 0; mi < 2; mi++) {
        #pragma unroll
        for (int h2 = 0; h2 < 2; h2++) {
            float m = acc[mi][0][h2 * 2];
            #pragma unroll
            for (int j = 0; j < 8; j++)
                m = fmaxf(m, fmaxf(acc[mi][j][h2 * 2], acc[mi][j][h2 * 2 + 1]));
            m = fmaxf(m, __shfl_xor_sync(0xffffffffu, m, 1));
            m = fmaxf(m, __shfl_xor_sync(0xffffffffu, m, 2));
            if (tk == 0) smax[(wm + mi * 16 + g + h2 * 8) * 2 + kh] = m;
        }
    }
    BAR_PAIR(barid);

    // ---- softmax part 2: exp, write P (own k-half region, 128 B rows);
    //      accumulate rowsum from the ROUNDED P; store via generic pointer ----
    {
        unsigned char* pptr = smb + (kh ? AT_QLO : AT_QHI);
        #pragma unroll
        for (int mi = 0; mi < 2; mi++) {
            #pragma unroll
            for (int h2 = 0; h2 < 2; h2++) {
                int row = wm + mi * 16 + g + h2 * 8;
                float M = fmaxf(smax[row * 2], smax[row * 2 + 1]);
                float s = 0.0f;
                #pragma unroll
                for (int j = 0; j < 8; j++) {
                    float x0 = __expf(acc[mi][j][h2 * 2]     - M);
                    float x1 = __expf(acc[mi][j][h2 * 2 + 1] - M);
                    uint32_t ph = cvt2h(x1, x0);
                    s += f16lo(ph) + f16hi(ph);
                    uint32_t off = SWZ128((uint32_t)(row * 128 + j * 16 + tk * 4));
                    *(uint32_t*)(pptr + off) = ph;
                }
                s += __shfl_xor_sync(0xffffffffu, s, 1);
                s += __shfl_xor_sync(0xffffffffu, s, 2);
                if (tk == 0) ssum[row * 2 + kh] = s;
            }
        }
    }
    BAR_PAIR(barid);

    // ---- GEMM2: out = P . VV; 1-pass (P single, V hi) ----
    float o[2][4][4];
    #pragma unroll
    for (int i = 0; i < 2; i++)
        #pragma unroll
        for (int j = 0; j < 4; j++)
            #pragma unroll
            for (int q = 0; q < 4; q++) o[i][j][q] = 0.0f;

    {
        const int wdh = kh * 32;
        #pragma unroll
        for (int ks = 0; ks < 8; ks++) {
            const uint32_t pbase = sbase + (ks < 4 ? AT_QHI : AT_QLO);
            uint32_t ah[2][4];
            #pragma unroll
            for (int mi = 0; mi < 2; mi++) {
                uint32_t off = SWZ128((uint32_t)((wm + mi * 16 + (lane & 15)) * 128
                                                 + (ks & 3) * 32 + (lane >> 4) * 16));
                LDSM4(ah[mi], pbase + off);
            }
            #pragma unroll
            for (int g2 = 0; g2 < 2; g2++) {
                uint32_t offb = SWZ128((uint32_t)((ks * 16 + (lane & 15)) * 128
                                                  + wdh * 2 + g2 * 32 + (lane >> 4) * 16));
                uint32_t bh[4];
                LDSM4T(bh, sbase + AT_VHI + offb);
                // trans B pairing: tile(g2*2)=(r0,r1), tile(g2*2+1)=(r2,r3)
                #pragma unroll
                for (int mi = 0; mi < 2; mi++) {
                    #pragma unroll
                    for (int jj = 0; jj < 2; jj++) {
                        float* cc = o[mi][g2 * 2 + jj];
                        MMA_F16(cc, ah[mi], bh[jj * 2], bh[jj * 2 + 1]);
                    }
                }
            }
        }
    }

    // ---- epilogue: normalize by 1/rowsum, store ----
    {
        const int wdh = kh * 32;
        const size_t obase = ((size_t)b * Nn + (size_t)nt * 128) * Dn + h * 64;
        #pragma unroll
        for (int mi = 0; mi < 2; mi++) {
            int r0 = wm + mi * 16 + g;
            int r1 = r0 + 8;
            float ri0 = 1.0f / (ssum[r0 * 2] + ssum[r0 * 2 + 1]);
            float ri1 = 1.0f / (ssum[r1 * 2] + ssum[r1 * 2 + 1]);
            #pragma unroll
            for (int j = 0; j < 4; j++) {
                int col = wdh + j * 8 + tk * 2;
                *(float2*)&outg[obase + (size_t)r0 * Dn + col] =
                    make_float2(o[mi][j][0] * ri0, o[mi][j][1] * ri0);
                *(float2*)&outg[obase + (size_t)r1 * Dn + col] =
                    make_float2(o[mi][j][2] * ri1, o[mi][j][3] * ri1);
            }
        }
    }
}

// ============================================================================
// Launch
// ============================================================================
extern "C" void kernel_launch(void* const* d_in, const int* in_sizes, int n_in,
                              void* d_out, int out_size)
{
    const float* q      = (const float*)d_in[0];
    const float* keys   = (const float*)d_in[1];
    const float* values = (const float*)d_in[2];
    const float* pk     = (const float*)d_in[3];
    const float* pv     = (const float*)d_in[4];
    float* out = (float*)d_out;

    cudaFuncSetAttribute(proj_mma_kernel,
                         cudaFuncAttributeMaxDynamicSharedMemorySize, PJ_SMEM);
    cudaFuncSetAttribute(attn_mma_kernel,
                         cudaFuncAttributeMaxDynamicSharedMemorySize, AT_SMEM);

    ptrans_kernel<<<dim3(Nn / 32, 2), 256>>>(pk, pv);
    proj_mma_kernel<<<dim3(8, Bsz, 2), 512, PJ_SMEM>>>(keys, values);
    attn_mma_kernel<<<dim3(Nn / 128, Hn, Bsz), 256, AT_SMEM>>>(q, out);
}